// round 13
// baseline (speedup 1.0000x reference)
#include <cuda_runtime.h>
#include <cuda_bf16.h>
#include <math.h>
#include <stdint.h>

// Problem constants (fixed: B=2, T=2048, DIM=2048, H=16, HKV=4, D=128)
#define BATCH 2
#define TLEN  2048
#define DIM   2048
#define NH    16
#define NKV   4
#define DH    128
#define MTOT  (BATCH * TLEN)
#define NQKV  (DIM + 2 * NKV * DH)     // 3072 packed output cols
#define NQT   (TLEN / 64)              // 32 query tiles
#define ATTN_SCALE 0.08838834764831845f
#define LOG2E 1.4426950408889634f
#define EPSF 1.1920929e-07f

// ---------------- scratch (device globals) ---------------------------------
__device__ float g_qkv[MTOT * NQKV];   // packed q|k|v fp32

__device__ __nv_bfloat16 g_xh[MTOT * DIM],   g_xl[MTOT * DIM];
__device__ __nv_bfloat16 g_wqkvh[NQKV * DIM], g_wqkvl[NQKV * DIM];
__device__ __nv_bfloat16 g_owh[DIM * DIM],   g_owl[DIM * DIM];
__device__ __nv_bfloat16 g_oh[MTOT * DIM],   g_ol[MTOT * DIM];

__device__ __nv_bfloat16 g_qbh[MTOT * DIM],      g_qbl[MTOT * DIM];
__device__ __nv_bfloat16 g_kbh[MTOT * NKV * DH], g_kbl[MTOT * NKV * DH];
__device__ __nv_bfloat16 g_vbh[MTOT * NKV * DH], g_vbl[MTOT * NKV * DH];

__device__ float g_cos[TLEN * 64];
__device__ float g_sin[TLEN * 64];

// ---------------------------------------------------------------------------
__device__ __forceinline__ uint32_t s2u(const void* p) {
    return (uint32_t)__cvta_generic_to_shared(p);
}
#define SWZ(o) ((o) ^ (((o) >> 3) & 0x70))

__device__ __forceinline__ void cp_async16(uint32_t saddr, const void* gaddr) {
    asm volatile("cp.async.cg.shared.global [%0], [%1], 16;\n"
                 :: "r"(saddr), "l"(gaddr));
}
__device__ __forceinline__ void ldsm4(uint32_t* r, uint32_t addr) {
    asm volatile("ldmatrix.sync.aligned.m8n8.x4.shared.b16 {%0,%1,%2,%3}, [%4];"
                 : "=r"(r[0]), "=r"(r[1]), "=r"(r[2]), "=r"(r[3]) : "r"(addr));
}
__device__ __forceinline__ void ldsm4t(uint32_t* r, uint32_t addr) {
    asm volatile("ldmatrix.sync.aligned.m8n8.x4.trans.shared.b16 {%0,%1,%2,%3}, [%4];"
                 : "=r"(r[0]), "=r"(r[1]), "=r"(r[2]), "=r"(r[3]) : "r"(addr));
}
__device__ __forceinline__ void ldsm2(uint32_t* r, uint32_t addr) {
    asm volatile("ldmatrix.sync.aligned.m8n8.x2.shared.b16 {%0,%1}, [%2];"
                 : "=r"(r[0]), "=r"(r[1]) : "r"(addr));
}
__device__ __forceinline__ void mma16816(float* c, const uint32_t* a, const uint32_t* b) {
    asm volatile(
        "mma.sync.aligned.m16n8k16.row.col.f32.bf16.bf16.f32 "
        "{%0,%1,%2,%3}, {%4,%5,%6,%7}, {%8,%9}, {%0,%1,%2,%3};"
        : "+f"(c[0]), "+f"(c[1]), "+f"(c[2]), "+f"(c[3])
        : "r"(a[0]), "r"(a[1]), "r"(a[2]), "r"(a[3]), "r"(b[0]), "r"(b[1]));
}
__device__ __forceinline__ uint32_t packbf(float a, float b) {
    __nv_bfloat162 t(__float2bfloat16(a), __float2bfloat16(b));
    return *(uint32_t*)&t;
}

// ---------------------------------------------------------------------------
// split fp32 -> bf16 hi + bf16 lo
// ---------------------------------------------------------------------------
__global__ __launch_bounds__(256) void split_bf16(
    const float* __restrict__ src, __nv_bfloat16* __restrict__ hi,
    __nv_bfloat16* __restrict__ lo, int n4)
{
    int i = blockIdx.x * 256 + threadIdx.x;
    if (i >= n4) return;
    float4 v = ((const float4*)src)[i];
    __nv_bfloat16 h0 = __float2bfloat16(v.x);
    __nv_bfloat16 h1 = __float2bfloat16(v.y);
    __nv_bfloat16 h2 = __float2bfloat16(v.z);
    __nv_bfloat16 h3 = __float2bfloat16(v.w);
    ((__nv_bfloat162*)hi)[2*i]   = __nv_bfloat162(h0, h1);
    ((__nv_bfloat162*)hi)[2*i+1] = __nv_bfloat162(h2, h3);
    ((__nv_bfloat162*)lo)[2*i] = __nv_bfloat162(
        __float2bfloat16(v.x - __bfloat162float(h0)),
        __float2bfloat16(v.y - __bfloat162float(h1)));
    ((__nv_bfloat162*)lo)[2*i+1] = __nv_bfloat162(
        __float2bfloat16(v.z - __bfloat162float(h2)),
        __float2bfloat16(v.w - __bfloat162float(h3)));
}

// ---------------------------------------------------------------------------
// pack q_w|k_w|v_w into one [3072,2048] hi/lo pair
// ---------------------------------------------------------------------------
__global__ __launch_bounds__(256) void prep_wqkv(
    const float* __restrict__ qw, const float* __restrict__ kw,
    const float* __restrict__ vw,
    __nv_bfloat16* __restrict__ hi, __nv_bfloat16* __restrict__ lo)
{
    int i = blockIdx.x * 256 + threadIdx.x;
    if (i >= NQKV * DIM / 4) return;
    int row = i >> 9;
    int c4  = i & 511;
    const float* src;
    if (row < DIM)            src = qw + (size_t)row * DIM;
    else if (row < DIM + 512) src = kw + (size_t)(row - DIM) * DIM;
    else                      src = vw + (size_t)(row - DIM - 512) * DIM;
    float4 v = ((const float4*)src)[c4];
    __nv_bfloat16 h0 = __float2bfloat16(v.x);
    __nv_bfloat16 h1 = __float2bfloat16(v.y);
    __nv_bfloat16 h2 = __float2bfloat16(v.z);
    __nv_bfloat16 h3 = __float2bfloat16(v.w);
    ((__nv_bfloat162*)hi)[2*i]   = __nv_bfloat162(h0, h1);
    ((__nv_bfloat162*)hi)[2*i+1] = __nv_bfloat162(h2, h3);
    ((__nv_bfloat162*)lo)[2*i] = __nv_bfloat162(
        __float2bfloat16(v.x - __bfloat162float(h0)),
        __float2bfloat16(v.y - __bfloat162float(h1)));
    ((__nv_bfloat162*)lo)[2*i+1] = __nv_bfloat162(
        __float2bfloat16(v.z - __bfloat162float(h2)),
        __float2bfloat16(v.w - __bfloat162float(h3)));
}

// ---------------------------------------------------------------------------
// HMMA GEMM (NT), bf16 3-split, 3-stage prefetch, SINGLE barrier per stage:
// load of stage s+2 is issued AFTER the barrier of stage s, so the trailing
// barrier (which guarded buffer (s+2)%3 == (s-1)%3 against overwrite while
// still being read in iteration s-1) is no longer needed — any warp past
// barrier s has finished its s-1 compute.
// ---------------------------------------------------------------------------
#define GSTAGE 32768
#define GEMM_SMEM (3 * GSTAGE)

__global__ __launch_bounds__(256) void gemm_tc(
    const __nv_bfloat16* __restrict__ Ah, const __nv_bfloat16* __restrict__ Al,
    const __nv_bfloat16* __restrict__ Bh, const __nv_bfloat16* __restrict__ Bl,
    float* __restrict__ C, int M, int N, int K)
{
    extern __shared__ char sm[];
    const uint32_t smem_base = s2u(sm);
    const int tid = threadIdx.x;
    const int wid = tid >> 5, lane = tid & 31;
    const int wm = wid >> 2, wn = wid & 3;
    const int bm = blockIdx.y * 128, bn = blockIdx.x * 128;

    const int kstages = K >> 6;
    const int S = 3 * kstages;

    float acc[4][4][4];
#pragma unroll
    for (int i = 0; i < 4; ++i)
#pragma unroll
        for (int j = 0; j < 4; ++j)
#pragma unroll
            for (int t = 0; t < 4; ++t) acc[i][j][t] = 0.f;

    const int l16 = lane & 15;
    uint32_t aOff[4], aMsk[4], bOff[4], bMsk[4];
#pragma unroll
    for (int mt = 0; mt < 4; ++mt) {
        int row = wm * 64 + mt * 16 + l16;
        aOff[mt] = row * 128;
        aMsk[mt] = (row & 7) << 4;
    }
#pragma unroll
    for (int nt = 0; nt < 4; ++nt) {
        int row = wn * 32 + nt * 8 + (l16 & 7);
        bOff[nt] = row * 128;
        bMsk[nt] = (row & 7) << 4;
    }
    const uint32_t kbA = (lane >> 4) * 16;
    const uint32_t kbB = ((l16 >> 3) & 1) * 16;

    auto load_stage = [&](int s) {
        int p = s / kstages;
        int ks = (s - p * kstages) << 6;
        const __nv_bfloat16* Ap = (p == 1) ? Al : Ah;
        const __nv_bfloat16* Bp = (p == 2) ? Bl : Bh;
        uint32_t abuf = smem_base + (s % 3) * GSTAGE;
        uint32_t bbuf = abuf + 16384;
#pragma unroll
        for (int i = 0; i < 4; ++i) {
            int c = tid + i * 256;
            int row = c >> 3, c16 = c & 7;
            cp_async16(abuf + SWZ(row * 128 + c16 * 16),
                       Ap + (size_t)(bm + row) * K + ks + c16 * 8);
        }
#pragma unroll
        for (int i = 0; i < 4; ++i) {
            int c = tid + i * 256;
            int row = c >> 3, c16 = c & 7;
            cp_async16(bbuf + SWZ(row * 128 + c16 * 16),
                       Bp + (size_t)(bn + row) * K + ks + c16 * 8);
        }
        asm volatile("cp.async.commit_group;");
    };

    load_stage(0);
    load_stage(1);
    for (int s = 0; s < S; ++s) {
        if (s + 1 < S) {
            asm volatile("cp.async.wait_group 1;" ::: "memory");  // stage s ready
        } else {
            asm volatile("cp.async.wait_group 0;" ::: "memory");
        }
        __syncthreads();
        if (s + 2 < S) load_stage(s + 2);   // safe: all warps finished s-1 reads

        uint32_t abuf = smem_base + (s % 3) * GSTAGE;
        uint32_t bbuf = abuf + 16384;
#pragma unroll
        for (int kk = 0; kk < 4; ++kk) {
            uint32_t af[4][4], bfr[4][2];
            uint32_t ka = kk * 32 + kbA;
            uint32_t kb = kk * 32 + kbB;
#pragma unroll
            for (int mt = 0; mt < 4; ++mt)
                ldsm4(af[mt], abuf + aOff[mt] + (ka ^ aMsk[mt]));
#pragma unroll
            for (int nt = 0; nt < 4; ++nt)
                ldsm2(bfr[nt], bbuf + bOff[nt] + (kb ^ bMsk[nt]));
#pragma unroll
            for (int mt = 0; mt < 4; ++mt)
#pragma unroll
                for (int nt = 0; nt < 4; ++nt)
                    mma16816(acc[mt][nt], af[mt], bfr[nt]);
        }
    }

    const int er = lane >> 2, ec = (lane & 3) * 2;
#pragma unroll
    for (int mt = 0; mt < 4; ++mt) {
#pragma unroll
        for (int nt = 0; nt < 4; ++nt) {
            int r0 = bm + wm * 64 + mt * 16 + er;
            int c0 = bn + wn * 32 + nt * 8 + ec;
            *(float2*)&C[(size_t)r0 * N + c0] =
                make_float2(acc[mt][nt][0], acc[mt][nt][1]);
            *(float2*)&C[(size_t)(r0 + 8) * N + c0] =
                make_float2(acc[mt][nt][2], acc[mt][nt][3]);
        }
    }
}

// ---------------------------------------------------------------------------
// RoPE tables (T x 64)
// ---------------------------------------------------------------------------
__global__ void rope_table_kernel(float* __restrict__ cs, float* __restrict__ sn)
{
    const int t = blockIdx.x, i = threadIdx.x;
    float base = 10000.f;
    if (TLEN > 1024) base = 10000.f * powf((float)TLEN / 1024.f, 128.f / 126.f);
    float l2b = log2f(base);
    float inv = exp2f(-(float)i * (l2b * (1.f / 64.f)));
    float ang = (float)t * inv;
    cs[t * 64 + i] = cosf(ang);
    sn[t * 64 + i] = sinf(ang);
}

// ---------------------------------------------------------------------------
// Fused RMSNorm + RoPE (+v split), 2 vectors per 256-thread block.
// ---------------------------------------------------------------------------
__global__ __launch_bounds__(256) void norm_rope_kernel(
    const float* __restrict__ qkv, const float* __restrict__ q_gain,
    const float* __restrict__ cs, const float* __restrict__ sn,
    __nv_bfloat16* __restrict__ qh, __nv_bfloat16* __restrict__ ql,
    __nv_bfloat16* __restrict__ kh, __nv_bfloat16* __restrict__ kl,
    __nv_bfloat16* __restrict__ vh, __nv_bfloat16* __restrict__ vl)
{
    const int sub = threadIdx.x >> 7;
    const int vec = blockIdx.x * 2 + sub;
    const int hh = vec % 24;
    const int token = vec / 24;
    const int t = token % TLEN;
    const int tid = threadIdx.x & 127;

    const float* src = qkv + (size_t)token * NQKV;
    __nv_bfloat16 *oh, *ol;
    size_t off;
    float gain;

    __shared__ float red[2][4];
    __shared__ float buf[2][DH];

    if (hh < NH) {
        src += hh * DH;
        off = ((size_t)token * NH + hh) * DH;
        oh = qh; ol = ql;
        gain = q_gain[hh] * (ATTN_SCALE * LOG2E);
    } else if (hh < NH + NKV) {
        src += DIM + (hh - NH) * DH;
        off = ((size_t)token * NKV + (hh - NH)) * DH;
        oh = kh; ol = kl;
        gain = 1.f;
    } else {
        src += DIM + NKV * DH + (hh - NH - NKV) * DH;
        off = ((size_t)token * NKV + (hh - NH - NKV)) * DH;
        float r = src[tid];
        __nv_bfloat16 hv = __float2bfloat16(r);
        vh[off + tid] = hv;
        vl[off + tid] = __float2bfloat16(r - __bfloat162float(hv));
        return;
    }

    float xv = src[tid];

    float s = xv * xv;
#pragma unroll
    for (int o = 16; o > 0; o >>= 1)
        s += __shfl_xor_sync(0xffffffffu, s, o);
    if ((tid & 31) == 0) red[sub][tid >> 5] = s;
    __syncthreads();
    float tot = red[sub][0] + red[sub][1] + red[sub][2] + red[sub][3];
    float rn = rsqrtf(tot * (1.f / DH) + EPSF);
    float xn = xv * rn;

    buf[sub][tid] = xn;
    __syncthreads();

    const int i = tid & 63;
    float c  = cs[t * 64 + i];
    float si = sn[t * 64 + i];
    float x1 = buf[sub][i], x2 = buf[sub][i + 64];
    float r = ((tid < 64) ? (x1 * c + x2 * si) : (-x1 * si + x2 * c)) * gain;

    __nv_bfloat16 hv = __float2bfloat16(r);
    oh[off + tid] = hv;
    ol[off + tid] = __float2bfloat16(r - __bfloat162float(hv));
}

// ---------------------------------------------------------------------------
// HMMA flash attention (causal, GQA), hi/lo split. (R6-validated form)
// ---------------------------------------------------------------------------
#define ATTN_SMEM (6 * 16384)

__global__ __launch_bounds__(128) void attn_mma(
    const __nv_bfloat16* __restrict__ qh, const __nv_bfloat16* __restrict__ ql,
    const __nv_bfloat16* __restrict__ kh, const __nv_bfloat16* __restrict__ kl,
    const __nv_bfloat16* __restrict__ vh, const __nv_bfloat16* __restrict__ vl,
    __nv_bfloat16* __restrict__ oh, __nv_bfloat16* __restrict__ ol)
{
    extern __shared__ char smc[];
    const uint32_t sQH = s2u(smc);
    const uint32_t sQL = sQH + 16384;
    const uint32_t sKH = sQL + 16384;
    const uint32_t sKL = sKH + 16384;
    const uint32_t sVH = sKL + 16384;
    const uint32_t sVL = sVH + 16384;

    const int pr = blockIdx.x;
    const int h = blockIdx.y, b = blockIdx.z;
    const int hkv = h >> 2;
    const int tid = threadIdx.x, wid = tid >> 5, lane = tid & 31;
    const int quad = lane >> 2, qx = lane & 3;

    const uint32_t aRow = wid * 16 + (lane & 15);
    const uint32_t aSwz = (aRow & 7) << 4;
    const uint32_t aKb  = (lane >> 4) * 16;
    const uint32_t kRowB = ((lane >> 4) & 1) * 8 + (lane & 7);
    const uint32_t kKb   = ((lane >> 3) & 1) * 16;
    const uint32_t vRowB = ((lane >> 3) & 1) * 8 + (lane & 7);
    const uint32_t vCb   = ((lane >> 4) & 1) * 16;

    for (int sel = 0; sel < 2; ++sel) {
        const int qb = sel ? (NQT - 1 - pr) : pr;
        const int q0 = qb * 64;

        __syncthreads();
        for (int i = tid; i < 1024; i += 128) {
            int row = i >> 4, cb = (i & 15) * 16;
            uint32_t sw = row * 256 + (cb ^ ((row & 7) << 4));
            size_t g = ((size_t)(b * TLEN + q0 + row) * NH + h) * DH + (i & 15) * 8;
            cp_async16(sQH + sw, qh + g);
            cp_async16(sQL + sw, ql + g);
        }
        asm volatile("cp.async.commit_group;");
        asm volatile("cp.async.wait_group 0;" ::: "memory");
        __syncthreads();

        uint32_t qfh[8][4], qfl[8][4];
#pragma unroll
        for (int kk = 0; kk < 8; ++kk) {
            ldsm4(qfh[kk], sQH + aRow * 256 + ((kk * 32 + aKb) ^ aSwz));
            ldsm4(qfl[kk], sQL + aRow * 256 + ((kk * 32 + aKb) ^ aSwz));
        }

        float acc[16][4];
#pragma unroll
        for (int j = 0; j < 16; ++j)
#pragma unroll
            for (int t = 0; t < 4; ++t) acc[j][t] = 0.f;
        float m0 = -1e30f, m1 = -1e30f, l0 = 0.f, l1 = 0.f;

        for (int kt = 0; kt <= qb; ++kt) {
            __syncthreads();
            for (int i = tid; i < 1024; i += 128) {
                int row = i >> 4, cb = (i & 15) * 16;
                uint32_t sw = row * 256 + (cb ^ ((row & 7) << 4));
                size_t g = ((size_t)(b * TLEN + kt * 64 + row) * NKV + hkv) * DH
                           + (i & 15) * 8;
                cp_async16(sKH + sw, kh + g);
                cp_async16(sKL + sw, kl + g);
                cp_async16(sVH + sw, vh + g);
                cp_async16(sVL + sw, vl + g);
            }
            asm volatile("cp.async.commit_group;");
            asm volatile("cp.async.wait_group 0;" ::: "memory");
            __syncthreads();

            float s[8][4];
#pragma unroll
            for (int j = 0; j < 8; ++j)
#pragma unroll
                for (int t = 0; t < 4; ++t) s[j][t] = 0.f;

#pragma unroll
            for (int kk = 0; kk < 8; ++kk) {
#pragma unroll
                for (int jj = 0; jj < 4; ++jj) {
                    uint32_t kr = jj * 16 + kRowB;
                    uint32_t off = kr * 256 + ((kk * 32 + kKb) ^ ((kr & 7) << 4));
                    uint32_t kf[4];
                    ldsm4(kf, sKH + off);
                    mma16816(s[2 * jj],     qfh[kk], kf);
                    mma16816(s[2 * jj + 1], qfh[kk], kf + 2);
                    mma16816(s[2 * jj],     qfl[kk], kf);
                    mma16816(s[2 * jj + 1], qfl[kk], kf + 2);
                    ldsm4(kf, sKL + off);
                    mma16816(s[2 * jj],     qfh[kk], kf);
                    mma16816(s[2 * jj + 1], qfh[kk], kf + 2);
                }
            }

            if (kt == qb) {
                int gr = wid * 16 + quad;
#pragma unroll
                for (int j = 0; j < 8; ++j) {
                    int gc = j * 8 + qx * 2;
                    if (gc     > gr)     s[j][0] = -1e30f;
                    if (gc + 1 > gr)     s[j][1] = -1e30f;
                    if (gc     > gr + 8) s[j][2] = -1e30f;
                    if (gc + 1 > gr + 8) s[j][3] = -1e30f;
                }
            }

            float t0 = -1e30f, t1 = -1e30f;
#pragma unroll
            for (int j = 0; j < 8; ++j) {
                t0 = fmaxf(t0, fmaxf(s[j][0], s[j][1]));
                t1 = fmaxf(t1, fmaxf(s[j][2], s[j][3]));
            }
            t0 = fmaxf(t0, __shfl_xor_sync(0xffffffffu, t0, 1));
            t0 = fmaxf(t0, __shfl_xor_sync(0xffffffffu, t0, 2));
            t1 = fmaxf(t1, __shfl_xor_sync(0xffffffffu, t1, 1));
            t1 = fmaxf(t1, __shfl_xor_sync(0xffffffffu, t1, 2));
            float mn0 = fmaxf(m0, t0), mn1 = fmaxf(m1, t1);
            float sc0 = exp2f(m0 - mn0), sc1 = exp2f(m1 - mn1);
            m0 = mn0; m1 = mn1;

            uint32_t phA[8], phB[8], plA[8], plB[8];
            float ls0 = 0.f, ls1 = 0.f;
#pragma unroll
            for (int j = 0; j < 8; ++j) {
                float p0 = exp2f(s[j][0] - mn0);
                float p1 = exp2f(s[j][1] - mn0);
                float p2 = exp2f(s[j][2] - mn1);
                float p3 = exp2f(s[j][3] - mn1);
                ls0 += p0 + p1; ls1 += p2 + p3;
                __nv_bfloat16 h0 = __float2bfloat16(p0), h1 = __float2bfloat16(p1);
                __nv_bfloat16 h2 = __float2bfloat16(p2), h3 = __float2bfloat16(p3);
                __nv_bfloat162 a(h0, h1), bb(h2, h3);
                phA[j] = *(uint32_t*)&a; phB[j] = *(uint32_t*)&bb;
                plA[j] = packbf(p0 - __bfloat162float(h0), p1 - __bfloat162float(h1));
                plB[j] = packbf(p2 - __bfloat162float(h2), p3 - __bfloat162float(h3));
            }
            l0 = l0 * sc0 + ls0;
            l1 = l1 * sc1 + ls1;
#pragma unroll
            for (int j = 0; j < 16; ++j) {
                acc[j][0] *= sc0; acc[j][1] *= sc0;
                acc[j][2] *= sc1; acc[j][3] *= sc1;
            }

#pragma unroll
            for (int kk = 0; kk < 4; ++kk) {
                uint32_t aH[4] = {phA[2*kk], phB[2*kk], phA[2*kk+1], phB[2*kk+1]};
                uint32_t aL[4] = {plA[2*kk], plB[2*kk], plA[2*kk+1], plB[2*kk+1]};
                uint32_t vr = kk * 16 + vRowB;
                uint32_t vsw = (vr & 7) << 4;
#pragma unroll
                for (int jp = 0; jp < 8; ++jp) {
                    uint32_t off = vr * 256 + ((jp * 32 + vCb) ^ vsw);
                    uint32_t vf[4];
                    ldsm4t(vf, sVH + off);
                    mma16816(acc[2 * jp],     aH, vf);
                    mma16816(acc[2 * jp + 1], aH, vf + 2);
                    mma16816(acc[2 * jp],     aL, vf);
                    mma16816(acc[2 * jp + 1], aL, vf + 2);
                    ldsm4t(vf, sVL + off);
                    mma16816(acc[2 * jp],     aH, vf);
                    mma16816(acc[2 * jp + 1], aH, vf + 2);
                }
            }
        }

        l0 += __shfl_xor_sync(0xffffffffu, l0, 1);
        l0 += __shfl_xor_sync(0xffffffffu, l0, 2);
        l1 += __shfl_xor_sync(0xffffffffu, l1, 1);
        l1 += __shfl_xor_sync(0xffffffffu, l1, 2);
        float i0 = 1.f / l0, i1 = 1.f / l1;

        size_t tok0 = (size_t)(b * TLEN + q0 + wid * 16 + quad);
        size_t tok1 = tok0 + 8;
#pragma unroll
        for (int j = 0; j < 16; ++j) {
            int col = h * DH + j * 8 + qx * 2;
            float v0 = acc[j][0] * i0, v1 = acc[j][1] * i0;
            float v2 = acc[j][2] * i1, v3 = acc[j][3] * i1;
            __nv_bfloat16 h0 = __float2bfloat16(v0), h1 = __float2bfloat16(v1);
            __nv_bfloat16 h2 = __float2bfloat16(v2), h3 = __float2bfloat16(v3);
            *(__nv_bfloat162*)&oh[tok0 * DIM + col] = __nv_bfloat162(h0, h1);
            *(__nv_bfloat162*)&oh[tok1 * DIM + col] = __nv_bfloat162(h2, h3);
            *(__nv_bfloat162*)&ol[tok0 * DIM + col] =
                __nv_bfloat162(__float2bfloat16(v0 - __bfloat162float(h0)),
                               __float2bfloat16(v1 - __bfloat162float(h1)));
            *(__nv_bfloat162*)&ol[tok1 * DIM + col] =
                __nv_bfloat162(__float2bfloat16(v2 - __bfloat162float(h2)),
                               __float2bfloat16(v3 - __bfloat162float(h3)));
        }
    }
}

// ---------------------------------------------------------------------------
extern "C" void kernel_launch(void* const* d_in, const int* in_sizes, int n_in,
                              void* d_out, int out_size)
{
    const float* x  = (const float*)d_in[0];
    const float* qw = (const float*)d_in[1];
    const float* kw = (const float*)d_in[2];
    const float* vw = (const float*)d_in[3];
    const float* ow = (const float*)d_in[4];
    const float* qg = (const float*)d_in[5];
    float* out = (float*)d_out;

    float *gqkv, *gcos, *gsin;
    cudaGetSymbolAddress((void**)&gqkv, g_qkv);
    cudaGetSymbolAddress((void**)&gcos, g_cos);
    cudaGetSymbolAddress((void**)&gsin, g_sin);

    __nv_bfloat16 *xh, *xl, *wqh, *wql, *owh, *owl, *oh, *ol;
    __nv_bfloat16 *qbh, *qbl, *kbh, *kbl, *vbh, *vbl;
    cudaGetSymbolAddress((void**)&xh,  g_xh);    cudaGetSymbolAddress((void**)&xl,  g_xl);
    cudaGetSymbolAddress((void**)&wqh, g_wqkvh); cudaGetSymbolAddress((void**)&wql, g_wqkvl);
    cudaGetSymbolAddress((void**)&owh, g_owh);   cudaGetSymbolAddress((void**)&owl, g_owl);
    cudaGetSymbolAddress((void**)&oh,  g_oh);    cudaGetSymbolAddress((void**)&ol,  g_ol);
    cudaGetSymbolAddress((void**)&qbh, g_qbh);   cudaGetSymbolAddress((void**)&qbl, g_qbl);
    cudaGetSymbolAddress((void**)&kbh, g_kbh);   cudaGetSymbolAddress((void**)&kbl, g_kbl);
    cudaGetSymbolAddress((void**)&vbh, g_vbh);   cudaGetSymbolAddress((void**)&vbl, g_vbl);

    const int M = MTOT, K = DIM;

    cudaFuncSetAttribute(gemm_tc, cudaFuncAttributeMaxDynamicSharedMemorySize, GEMM_SMEM);
    cudaFuncSetAttribute(attn_mma, cudaFuncAttributeMaxDynamicSharedMemorySize, ATTN_SMEM);

    rope_table_kernel<<<TLEN, 64>>>(gcos, gsin);                         // 0
    split_bf16<<<(M*K/4 + 255)/256, 256>>>(x, xh, xl, M*K/4);            // 1
    prep_wqkv<<<(NQKV*DIM/4 + 255)/256, 256>>>(qw, kw, vw, wqh, wql);    // 2
    gemm_tc<<<dim3(NQKV/128, M/128), 256, GEMM_SMEM>>>(                   // 3
        xh, xl, wqh, wql, gqkv, M, NQKV, K);
    norm_rope_kernel<<<M * 12, 256>>>(gqkv, qg, gcos, gsin,              // 4
                                      qbh, qbl, kbh, kbl, vbh, vbl);
    attn_mma<<<dim3(NQT/2, NH, BATCH), 128, ATTN_SMEM>>>(                 // 5
        qbh, qbl, kbh, kbl, vbh, vbl, oh, ol);
    split_bf16<<<(DIM*DIM/4 + 255)/256, 256>>>(ow, owh, owl, DIM*DIM/4); // 6
    gemm_tc<<<dim3(DIM/128, M/128), 256, GEMM_SMEM>>>(                    // 7
        oh, ol, owh, owl, out, M, DIM, K);
}

// round 14
// speedup vs baseline: 1.2487x; 1.2487x over previous
#include <cuda_runtime.h>
#include <cuda_fp16.h>
#include <math.h>
#include <stdint.h>

// Problem constants (fixed: B=2, T=2048, DIM=2048, H=16, HKV=4, D=128)
#define BATCH 2
#define TLEN  2048
#define DIM   2048
#define NH    16
#define NKV   4
#define DH    128
#define MTOT  (BATCH * TLEN)
#define NQKV  (DIM + 2 * NKV * DH)     // 3072 packed output cols
#define NQT   (TLEN / 64)              // 32 query tiles
#define ATTN_SCALE 0.08838834764831845f
#define LOG2E 1.4426950408889634f
#define EPSF 1.1920929e-07f

// ---------------- scratch (device globals) ---------------------------------
__device__ float g_qkv[MTOT * NQKV];   // packed q|k|v fp32

__device__ __half g_xh[MTOT * DIM],  g_xl[MTOT * DIM];
__device__ __half g_wqkvh[NQKV * DIM];                 // weights: hi only
__device__ __half g_owh[DIM * DIM],  g_owl[DIM * DIM]; // out-proj: hi+lo
__device__ __half g_oh[MTOT * DIM],  g_ol[MTOT * DIM];

__device__ __half g_qbh[MTOT * DIM], g_qbl[MTOT * DIM];
__device__ __half g_kbh[MTOT * NKV * DH];              // K: hi only
__device__ __half g_vbh[MTOT * NKV * DH];              // V: hi only

__device__ float g_cos[TLEN * 64];
__device__ float g_sin[TLEN * 64];

// ---------------------------------------------------------------------------
__device__ __forceinline__ uint32_t s2u(const void* p) {
    return (uint32_t)__cvta_generic_to_shared(p);
}
#define SWZ(o) ((o) ^ (((o) >> 3) & 0x70))

__device__ __forceinline__ void cp_async16(uint32_t saddr, const void* gaddr) {
    asm volatile("cp.async.cg.shared.global [%0], [%1], 16;\n"
                 :: "r"(saddr), "l"(gaddr));
}
__device__ __forceinline__ void ldsm4(uint32_t* r, uint32_t addr) {
    asm volatile("ldmatrix.sync.aligned.m8n8.x4.shared.b16 {%0,%1,%2,%3}, [%4];"
                 : "=r"(r[0]), "=r"(r[1]), "=r"(r[2]), "=r"(r[3]) : "r"(addr));
}
__device__ __forceinline__ void ldsm4t(uint32_t* r, uint32_t addr) {
    asm volatile("ldmatrix.sync.aligned.m8n8.x4.trans.shared.b16 {%0,%1,%2,%3}, [%4];"
                 : "=r"(r[0]), "=r"(r[1]), "=r"(r[2]), "=r"(r[3]) : "r"(addr));
}
__device__ __forceinline__ void ldsm2(uint32_t* r, uint32_t addr) {
    asm volatile("ldmatrix.sync.aligned.m8n8.x2.shared.b16 {%0,%1}, [%2];"
                 : "=r"(r[0]), "=r"(r[1]) : "r"(addr));
}
// fp16 MMA, fp32 accumulate
__device__ __forceinline__ void mma16816(float* c, const uint32_t* a, const uint32_t* b) {
    asm volatile(
        "mma.sync.aligned.m16n8k16.row.col.f32.f16.f16.f32 "
        "{%0,%1,%2,%3}, {%4,%5,%6,%7}, {%8,%9}, {%0,%1,%2,%3};"
        : "+f"(c[0]), "+f"(c[1]), "+f"(c[2]), "+f"(c[3])
        : "r"(a[0]), "r"(a[1]), "r"(a[2]), "r"(a[3]), "r"(b[0]), "r"(b[1]));
}
__device__ __forceinline__ uint32_t packhf(float a, float b) {
    __half2 t(__float2half(a), __float2half(b));
    return *(uint32_t*)&t;
}

// ---------------------------------------------------------------------------
// split fp32 -> fp16 hi + fp16 lo
// ---------------------------------------------------------------------------
__global__ __launch_bounds__(256) void split_fp16(
    const float* __restrict__ src, __half* __restrict__ hi,
    __half* __restrict__ lo, int n4)
{
    int i = blockIdx.x * 256 + threadIdx.x;
    if (i >= n4) return;
    float4 v = ((const float4*)src)[i];
    __half h0 = __float2half(v.x);
    __half h1 = __float2half(v.y);
    __half h2 = __float2half(v.z);
    __half h3 = __float2half(v.w);
    ((__half2*)hi)[2*i]   = __half2(h0, h1);
    ((__half2*)hi)[2*i+1] = __half2(h2, h3);
    ((__half2*)lo)[2*i] = __half2(
        __float2half(v.x - __half2float(h0)),
        __float2half(v.y - __half2float(h1)));
    ((__half2*)lo)[2*i+1] = __half2(
        __float2half(v.z - __half2float(h2)),
        __float2half(v.w - __half2float(h3)));
}

// ---------------------------------------------------------------------------
// pack q_w|k_w|v_w into one [3072,2048] fp16 (hi only)
// ---------------------------------------------------------------------------
__global__ __launch_bounds__(256) void prep_wqkv(
    const float* __restrict__ qw, const float* __restrict__ kw,
    const float* __restrict__ vw, __half* __restrict__ hi)
{
    int i = blockIdx.x * 256 + threadIdx.x;
    if (i >= NQKV * DIM / 4) return;
    int row = i >> 9;
    int c4  = i & 511;
    const float* src;
    if (row < DIM)            src = qw + (size_t)row * DIM;
    else if (row < DIM + 512) src = kw + (size_t)(row - DIM) * DIM;
    else                      src = vw + (size_t)(row - DIM - 512) * DIM;
    float4 v = ((const float4*)src)[c4];
    ((__half2*)hi)[2*i]   = __half2(__float2half(v.x), __float2half(v.y));
    ((__half2*)hi)[2*i+1] = __half2(__float2half(v.z), __float2half(v.w));
}

// ---------------------------------------------------------------------------
// HMMA GEMM (NT), fp16 split, npass in {2,3}:
//   npass=2: C = Ah*Bh + Al*Bh          (B single fp16)
//   npass=3: C = Ah*Bh + Al*Bh + Ah*Bl  (both split)
// 128x128 CTA tile, BK=64, 8 warps, 3-stage prefetch. (R10-validated core)
// ---------------------------------------------------------------------------
#define GSTAGE 32768
#define GEMM_SMEM (3 * GSTAGE)

__global__ __launch_bounds__(256) void gemm_tc(
    const __half* __restrict__ Ah, const __half* __restrict__ Al,
    const __half* __restrict__ Bh, const __half* __restrict__ Bl,
    float* __restrict__ C, int M, int N, int K, int npass)
{
    extern __shared__ char sm[];
    const uint32_t smem_base = s2u(sm);
    const int tid = threadIdx.x;
    const int wid = tid >> 5, lane = tid & 31;
    const int wm = wid >> 2, wn = wid & 3;
    const int bm = blockIdx.y * 128, bn = blockIdx.x * 128;

    const int kstages = K >> 6;
    const int S = npass * kstages;

    float acc[4][4][4];
#pragma unroll
    for (int i = 0; i < 4; ++i)
#pragma unroll
        for (int j = 0; j < 4; ++j)
#pragma unroll
            for (int t = 0; t < 4; ++t) acc[i][j][t] = 0.f;

    const int l16 = lane & 15;
    uint32_t aOff[4], aMsk[4], bOff[4], bMsk[4];
#pragma unroll
    for (int mt = 0; mt < 4; ++mt) {
        int row = wm * 64 + mt * 16 + l16;
        aOff[mt] = row * 128;
        aMsk[mt] = (row & 7) << 4;
    }
#pragma unroll
    for (int nt = 0; nt < 4; ++nt) {
        int row = wn * 32 + nt * 8 + (l16 & 7);
        bOff[nt] = row * 128;
        bMsk[nt] = (row & 7) << 4;
    }
    const uint32_t kbA = (lane >> 4) * 16;
    const uint32_t kbB = ((l16 >> 3) & 1) * 16;

    auto load_stage = [&](int s) {
        int p = s / kstages;
        int ks = (s - p * kstages) << 6;
        const __half* Ap = (p == 1) ? Al : Ah;
        const __half* Bp = (p == 2) ? Bl : Bh;
        uint32_t abuf = smem_base + (s % 3) * GSTAGE;
        uint32_t bbuf = abuf + 16384;
#pragma unroll
        for (int i = 0; i < 4; ++i) {
            int c = tid + i * 256;
            int row = c >> 3, c16 = c & 7;
            cp_async16(abuf + SWZ(row * 128 + c16 * 16),
                       Ap + (size_t)(bm + row) * K + ks + c16 * 8);
        }
#pragma unroll
        for (int i = 0; i < 4; ++i) {
            int c = tid + i * 256;
            int row = c >> 3, c16 = c & 7;
            cp_async16(bbuf + SWZ(row * 128 + c16 * 16),
                       Bp + (size_t)(bn + row) * K + ks + c16 * 8);
        }
        asm volatile("cp.async.commit_group;");
    };

    load_stage(0);
    load_stage(1);
    for (int s = 0; s < S; ++s) {
        if (s + 2 < S) {
            load_stage(s + 2);
            asm volatile("cp.async.wait_group 2;" ::: "memory");
        } else if (s + 1 < S) {
            asm volatile("cp.async.wait_group 1;" ::: "memory");
        } else {
            asm volatile("cp.async.wait_group 0;" ::: "memory");
        }
        __syncthreads();

        uint32_t abuf = smem_base + (s % 3) * GSTAGE;
        uint32_t bbuf = abuf + 16384;
#pragma unroll
        for (int kk = 0; kk < 4; ++kk) {
            uint32_t af[4][4], bfr[4][2];
            uint32_t ka = kk * 32 + kbA;
            uint32_t kb = kk * 32 + kbB;
#pragma unroll
            for (int mt = 0; mt < 4; ++mt)
                ldsm4(af[mt], abuf + aOff[mt] + (ka ^ aMsk[mt]));
#pragma unroll
            for (int nt = 0; nt < 4; ++nt)
                ldsm2(bfr[nt], bbuf + bOff[nt] + (kb ^ bMsk[nt]));
#pragma unroll
            for (int mt = 0; mt < 4; ++mt)
#pragma unroll
                for (int nt = 0; nt < 4; ++nt)
                    mma16816(acc[mt][nt], af[mt], bfr[nt]);
        }
        __syncthreads();
    }

    const int er = lane >> 2, ec = (lane & 3) * 2;
#pragma unroll
    for (int mt = 0; mt < 4; ++mt) {
#pragma unroll
        for (int nt = 0; nt < 4; ++nt) {
            int r0 = bm + wm * 64 + mt * 16 + er;
            int c0 = bn + wn * 32 + nt * 8 + ec;
            *(float2*)&C[(size_t)r0 * N + c0] =
                make_float2(acc[mt][nt][0], acc[mt][nt][1]);
            *(float2*)&C[(size_t)(r0 + 8) * N + c0] =
                make_float2(acc[mt][nt][2], acc[mt][nt][3]);
        }
    }
}

// ---------------------------------------------------------------------------
// RoPE tables (T x 64)
// ---------------------------------------------------------------------------
__global__ void rope_table_kernel(float* __restrict__ cs, float* __restrict__ sn)
{
    const int t = blockIdx.x, i = threadIdx.x;
    float base = 10000.f;
    if (TLEN > 1024) base = 10000.f * powf((float)TLEN / 1024.f, 128.f / 126.f);
    float l2b = log2f(base);
    float inv = exp2f(-(float)i * (l2b * (1.f / 64.f)));
    float ang = (float)t * inv;
    cs[t * 64 + i] = cosf(ang);
    sn[t * 64 + i] = sinf(ang);
}

// ---------------------------------------------------------------------------
// Fused RMSNorm + RoPE (+v pass-through), 2 vectors per 256-thread block.
// q -> fp16 hi/lo; k -> fp16 hi only; v -> fp16 hi only.
// ---------------------------------------------------------------------------
__global__ __launch_bounds__(256) void norm_rope_kernel(
    const float* __restrict__ qkv, const float* __restrict__ q_gain,
    const float* __restrict__ cs, const float* __restrict__ sn,
    __half* __restrict__ qh, __half* __restrict__ ql,
    __half* __restrict__ kh, __half* __restrict__ vh)
{
    const int sub = threadIdx.x >> 7;
    const int vec = blockIdx.x * 2 + sub;
    const int hh = vec % 24;
    const int token = vec / 24;
    const int t = token % TLEN;
    const int tid = threadIdx.x & 127;

    const float* src = qkv + (size_t)token * NQKV;
    size_t off;
    float gain;
    bool isq;

    __shared__ float red[2][4];
    __shared__ float buf[2][DH];

    if (hh < NH) {
        src += hh * DH;
        off = ((size_t)token * NH + hh) * DH;
        gain = q_gain[hh] * (ATTN_SCALE * LOG2E);
        isq = true;
    } else if (hh < NH + NKV) {
        src += DIM + (hh - NH) * DH;
        off = ((size_t)token * NKV + (hh - NH)) * DH;
        gain = 1.f;
        isq = false;
    } else {
        src += DIM + NKV * DH + (hh - NH - NKV) * DH;
        off = ((size_t)token * NKV + (hh - NH - NKV)) * DH;
        vh[off + tid] = __float2half(src[tid]);
        return;
    }

    float xv = src[tid];

    float s = xv * xv;
#pragma unroll
    for (int o = 16; o > 0; o >>= 1)
        s += __shfl_xor_sync(0xffffffffu, s, o);
    if ((tid & 31) == 0) red[sub][tid >> 5] = s;
    __syncthreads();
    float tot = red[sub][0] + red[sub][1] + red[sub][2] + red[sub][3];
    float rn = rsqrtf(tot * (1.f / DH) + EPSF);
    float xn = xv * rn;

    buf[sub][tid] = xn;
    __syncthreads();

    const int i = tid & 63;
    float c  = cs[t * 64 + i];
    float si = sn[t * 64 + i];
    float x1 = buf[sub][i], x2 = buf[sub][i + 64];
    float r = ((tid < 64) ? (x1 * c + x2 * si) : (-x1 * si + x2 * c)) * gain;

    if (isq) {
        __half hv = __float2half(r);
        qh[off + tid] = hv;
        ql[off + tid] = __float2half(r - __half2float(hv));
    } else {
        kh[off + tid] = __float2half(r);
    }
}

// ---------------------------------------------------------------------------
// HMMA flash attention (causal, GQA), fp16 2-term:
//   S = (qh+ql)*Kh ;  O += (ph+pl)*Vh
// smem: Q hi/lo 2x16KB + K 16KB + V 16KB = 64KB -> 3 CTA/SM.
// ---------------------------------------------------------------------------
#define ATTN_SMEM (4 * 16384)

__global__ __launch_bounds__(128) void attn_mma(
    const __half* __restrict__ qh, const __half* __restrict__ ql,
    const __half* __restrict__ kh, const __half* __restrict__ vh,
    __half* __restrict__ oh, __half* __restrict__ ol)
{
    extern __shared__ char smc[];
    const uint32_t sQH = s2u(smc);
    const uint32_t sQL = sQH + 16384;
    const uint32_t sKH = sQL + 16384;
    const uint32_t sVH = sKH + 16384;

    const int pr = blockIdx.x;
    const int h = blockIdx.y, b = blockIdx.z;
    const int hkv = h >> 2;
    const int tid = threadIdx.x, wid = tid >> 5, lane = tid & 31;
    const int quad = lane >> 2, qx = lane & 3;

    const uint32_t aRow = wid * 16 + (lane & 15);
    const uint32_t aSwz = (aRow & 7) << 4;
    const uint32_t aKb  = (lane >> 4) * 16;
    const uint32_t kRowB = ((lane >> 4) & 1) * 8 + (lane & 7);
    const uint32_t kKb   = ((lane >> 3) & 1) * 16;
    const uint32_t vRowB = ((lane >> 3) & 1) * 8 + (lane & 7);
    const uint32_t vCb   = ((lane >> 4) & 1) * 16;

    for (int sel = 0; sel < 2; ++sel) {
        const int qb = sel ? (NQT - 1 - pr) : pr;
        const int q0 = qb * 64;

        __syncthreads();
        for (int i = tid; i < 1024; i += 128) {
            int row = i >> 4, cb = (i & 15) * 16;
            uint32_t sw = row * 256 + (cb ^ ((row & 7) << 4));
            size_t g = ((size_t)(b * TLEN + q0 + row) * NH + h) * DH + (i & 15) * 8;
            cp_async16(sQH + sw, qh + g);
            cp_async16(sQL + sw, ql + g);
        }
        asm volatile("cp.async.commit_group;");
        asm volatile("cp.async.wait_group 0;" ::: "memory");
        __syncthreads();

        uint32_t qfh[8][4], qfl[8][4];
#pragma unroll
        for (int kk = 0; kk < 8; ++kk) {
            ldsm4(qfh[kk], sQH + aRow * 256 + ((kk * 32 + aKb) ^ aSwz));
            ldsm4(qfl[kk], sQL + aRow * 256 + ((kk * 32 + aKb) ^ aSwz));
        }

        float acc[16][4];
#pragma unroll
        for (int j = 0; j < 16; ++j)
#pragma unroll
            for (int t = 0; t < 4; ++t) acc[j][t] = 0.f;
        float m0 = -1e30f, m1 = -1e30f, l0 = 0.f, l1 = 0.f;

        for (int kt = 0; kt <= qb; ++kt) {
            __syncthreads();
            for (int i = tid; i < 1024; i += 128) {
                int row = i >> 4, cb = (i & 15) * 16;
                uint32_t sw = row * 256 + (cb ^ ((row & 7) << 4));
                size_t g = ((size_t)(b * TLEN + kt * 64 + row) * NKV + hkv) * DH
                           + (i & 15) * 8;
                cp_async16(sKH + sw, kh + g);
                cp_async16(sVH + sw, vh + g);
            }
            asm volatile("cp.async.commit_group;");
            asm volatile("cp.async.wait_group 0;" ::: "memory");
            __syncthreads();

            float s[8][4];
#pragma unroll
            for (int j = 0; j < 8; ++j)
#pragma unroll
                for (int t = 0; t < 4; ++t) s[j][t] = 0.f;

#pragma unroll
            for (int kk = 0; kk < 8; ++kk) {
#pragma unroll
                for (int jj = 0; jj < 4; ++jj) {
                    uint32_t kr = jj * 16 + kRowB;
                    uint32_t off = kr * 256 + ((kk * 32 + kKb) ^ ((kr & 7) << 4));
                    uint32_t kf[4];
                    ldsm4(kf, sKH + off);
                    mma16816(s[2 * jj],     qfh[kk], kf);
                    mma16816(s[2 * jj + 1], qfh[kk], kf + 2);
                    mma16816(s[2 * jj],     qfl[kk], kf);
                    mma16816(s[2 * jj + 1], qfl[kk], kf + 2);
                }
            }

            if (kt == qb) {
                int gr = wid * 16 + quad;
#pragma unroll
                for (int j = 0; j < 8; ++j) {
                    int gc = j * 8 + qx * 2;
                    if (gc     > gr)     s[j][0] = -1e30f;
                    if (gc + 1 > gr)     s[j][1] = -1e30f;
                    if (gc     > gr + 8) s[j][2] = -1e30f;
                    if (gc + 1 > gr + 8) s[j][3] = -1e30f;
                }
            }

            float t0 = -1e30f, t1 = -1e30f;
#pragma unroll
            for (int j = 0; j < 8; ++j) {
                t0 = fmaxf(t0, fmaxf(s[j][0], s[j][1]));
                t1 = fmaxf(t1, fmaxf(s[j][2], s[j][3]));
            }
            t0 = fmaxf(t0, __shfl_xor_sync(0xffffffffu, t0, 1));
            t0 = fmaxf(t0, __shfl_xor_sync(0xffffffffu, t0, 2));
            t1 = fmaxf(t1, __shfl_xor_sync(0xffffffffu, t1, 1));
            t1 = fmaxf(t1, __shfl_xor_sync(0xffffffffu, t1, 2));
            float mn0 = fmaxf(m0, t0), mn1 = fmaxf(m1, t1);
            float sc0 = exp2f(m0 - mn0), sc1 = exp2f(m1 - mn1);
            m0 = mn0; m1 = mn1;

            uint32_t phA[8], phB[8], plA[8], plB[8];
            float ls0 = 0.f, ls1 = 0.f;
#pragma unroll
            for (int j = 0; j < 8; ++j) {
                float p0 = exp2f(s[j][0] - mn0);
                float p1 = exp2f(s[j][1] - mn0);
                float p2 = exp2f(s[j][2] - mn1);
                float p3 = exp2f(s[j][3] - mn1);
                ls0 += p0 + p1; ls1 += p2 + p3;
                __half h0 = __float2half(p0), h1 = __float2half(p1);
                __half h2 = __float2half(p2), h3 = __float2half(p3);
                __half2 a(h0, h1), bb(h2, h3);
                phA[j] = *(uint32_t*)&a; phB[j] = *(uint32_t*)&bb;
                plA[j] = packhf(p0 - __half2float(h0), p1 - __half2float(h1));
                plB[j] = packhf(p2 - __half2float(h2), p3 - __half2float(h3));
            }
            l0 = l0 * sc0 + ls0;
            l1 = l1 * sc1 + ls1;
#pragma unroll
            for (int j = 0; j < 16; ++j) {
                acc[j][0] *= sc0; acc[j][1] *= sc0;
                acc[j][2] *= sc1; acc[j][3] *= sc1;
            }

#pragma unroll
            for (int kk = 0; kk < 4; ++kk) {
                uint32_t aH[4] = {phA[2*kk], phB[2*kk], phA[2*kk+1], phB[2*kk+1]};
                uint32_t aL[4] = {plA[2*kk], plB[2*kk], plA[2*kk+1], plB[2*kk+1]};
                uint32_t vr = kk * 16 + vRowB;
                uint32_t vsw = (vr & 7) << 4;
#pragma unroll
                for (int jp = 0; jp < 8; ++jp) {
                    uint32_t off = vr * 256 + ((jp * 32 + vCb) ^ vsw);
                    uint32_t vf[4];
                    ldsm4t(vf, sVH + off);
                    mma16816(acc[2 * jp],     aH, vf);
                    mma16816(acc[2 * jp + 1], aH, vf + 2);
                    mma16816(acc[2 * jp],     aL, vf);
                    mma16816(acc[2 * jp + 1], aL, vf + 2);
                }
            }
        }

        l0 += __shfl_xor_sync(0xffffffffu, l0, 1);
        l0 += __shfl_xor_sync(0xffffffffu, l0, 2);
        l1 += __shfl_xor_sync(0xffffffffu, l1, 1);
        l1 += __shfl_xor_sync(0xffffffffu, l1, 2);
        float i0 = 1.f / l0, i1 = 1.f / l1;

        size_t tok0 = (size_t)(b * TLEN + q0 + wid * 16 + quad);
        size_t tok1 = tok0 + 8;
#pragma unroll
        for (int j = 0; j < 16; ++j) {
            int col = h * DH + j * 8 + qx * 2;
            float v0 = acc[j][0] * i0, v1 = acc[j][1] * i0;
            float v2 = acc[j][2] * i1, v3 = acc[j][3] * i1;
            __half h0 = __float2half(v0), h1 = __float2half(v1);
            __half h2 = __float2half(v2), h3 = __float2half(v3);
            *(__half2*)&oh[tok0 * DIM + col] = __half2(h0, h1);
            *(__half2*)&oh[tok1 * DIM + col] = __half2(h2, h3);
            *(__half2*)&ol[tok0 * DIM + col] =
                __half2(__float2half(v0 - __half2float(h0)),
                        __float2half(v1 - __half2float(h1)));
            *(__half2*)&ol[tok1 * DIM + col] =
                __half2(__float2half(v2 - __half2float(h2)),
                        __float2half(v3 - __half2float(h3)));
        }
    }
}

// ---------------------------------------------------------------------------
extern "C" void kernel_launch(void* const* d_in, const int* in_sizes, int n_in,
                              void* d_out, int out_size)
{
    const float* x  = (const float*)d_in[0];
    const float* qw = (const float*)d_in[1];
    const float* kw = (const float*)d_in[2];
    const float* vw = (const float*)d_in[3];
    const float* ow = (const float*)d_in[4];
    const float* qg = (const float*)d_in[5];
    float* out = (float*)d_out;

    float *gqkv, *gcos, *gsin;
    cudaGetSymbolAddress((void**)&gqkv, g_qkv);
    cudaGetSymbolAddress((void**)&gcos, g_cos);
    cudaGetSymbolAddress((void**)&gsin, g_sin);

    __half *xh, *xl, *wqh, *owh, *owl, *oh, *ol;
    __half *qbh, *qbl, *kbh, *vbh;
    cudaGetSymbolAddress((void**)&xh,  g_xh);    cudaGetSymbolAddress((void**)&xl,  g_xl);
    cudaGetSymbolAddress((void**)&wqh, g_wqkvh);
    cudaGetSymbolAddress((void**)&owh, g_owh);   cudaGetSymbolAddress((void**)&owl, g_owl);
    cudaGetSymbolAddress((void**)&oh,  g_oh);    cudaGetSymbolAddress((void**)&ol,  g_ol);
    cudaGetSymbolAddress((void**)&qbh, g_qbh);   cudaGetSymbolAddress((void**)&qbl, g_qbl);
    cudaGetSymbolAddress((void**)&kbh, g_kbh);   cudaGetSymbolAddress((void**)&vbh, g_vbh);

    const int M = MTOT, K = DIM;

    cudaFuncSetAttribute(gemm_tc, cudaFuncAttributeMaxDynamicSharedMemorySize, GEMM_SMEM);
    cudaFuncSetAttribute(attn_mma, cudaFuncAttributeMaxDynamicSharedMemorySize, ATTN_SMEM);

    rope_table_kernel<<<TLEN, 64>>>(gcos, gsin);                           // 0
    split_fp16<<<(M*K/4 + 255)/256, 256>>>(x, xh, xl, M*K/4);              // 1
    prep_wqkv<<<(NQKV*DIM/4 + 255)/256, 256>>>(qw, kw, vw, wqh);           // 2
    gemm_tc<<<dim3(NQKV/128, M/128), 256, GEMM_SMEM>>>(                     // 3
        xh, xl, wqh, wqh, gqkv, M, NQKV, K, 2);
    norm_rope_kernel<<<M * 12, 256>>>(gqkv, qg, gcos, gsin,                // 4
                                      qbh, qbl, kbh, vbh);
    attn_mma<<<dim3(NQT/2, NH, BATCH), 128, ATTN_SMEM>>>(                   // 5
        qbh, qbl, kbh, vbh, oh, ol);
    split_fp16<<<(DIM*DIM/4 + 255)/256, 256>>>(ow, owh, owl, DIM*DIM/4);   // 6
    gemm_tc<<<dim3(DIM/128, M/128), 256, GEMM_SMEM>>>(                      // 7
        oh, ol, owh, owl, out, M, DIM, K, 3);
}

// round 15
// speedup vs baseline: 1.3991x; 1.1205x over previous
#include <cuda_runtime.h>
#include <cuda_fp16.h>
#include <math.h>
#include <stdint.h>

// Problem constants (fixed: B=2, T=2048, DIM=2048, H=16, HKV=4, D=128)
#define BATCH 2
#define TLEN  2048
#define DIM   2048
#define NH    16
#define NKV   4
#define DH    128
#define MTOT  (BATCH * TLEN)
#define NQKV  (DIM + 2 * NKV * DH)     // 3072 packed output cols
#define NQT   (TLEN / 64)              // 32 query tiles
#define ATTN_SCALE 0.08838834764831845f
#define LOG2E 1.4426950408889634f
#define EPSF 1.1920929e-07f

// ---------------- scratch (device globals) ---------------------------------
__device__ float g_qkv[MTOT * NQKV];   // packed q|k|v fp32

__device__ __half g_xh[MTOT * DIM],  g_xl[MTOT * DIM];
__device__ __half g_wqkvh[NQKV * DIM];                 // weights: hi only
__device__ __half g_owh[DIM * DIM];                    // out-proj W: hi only
__device__ __half g_oh[MTOT * DIM],  g_ol[MTOT * DIM];

__device__ __half g_qbh[MTOT * DIM], g_qbl[MTOT * DIM];
__device__ __half g_kbh[MTOT * NKV * DH];              // K: hi only
__device__ __half g_vbh[MTOT * NKV * DH];              // V: hi only

__device__ float g_cos[TLEN * 64];
__device__ float g_sin[TLEN * 64];

// ---------------------------------------------------------------------------
__device__ __forceinline__ uint32_t s2u(const void* p) {
    return (uint32_t)__cvta_generic_to_shared(p);
}
#define SWZ(o) ((o) ^ (((o) >> 3) & 0x70))

__device__ __forceinline__ void cp_async16(uint32_t saddr, const void* gaddr) {
    asm volatile("cp.async.cg.shared.global [%0], [%1], 16;\n"
                 :: "r"(saddr), "l"(gaddr));
}
__device__ __forceinline__ void ldsm4(uint32_t* r, uint32_t addr) {
    asm volatile("ldmatrix.sync.aligned.m8n8.x4.shared.b16 {%0,%1,%2,%3}, [%4];"
                 : "=r"(r[0]), "=r"(r[1]), "=r"(r[2]), "=r"(r[3]) : "r"(addr));
}
__device__ __forceinline__ void ldsm4t(uint32_t* r, uint32_t addr) {
    asm volatile("ldmatrix.sync.aligned.m8n8.x4.trans.shared.b16 {%0,%1,%2,%3}, [%4];"
                 : "=r"(r[0]), "=r"(r[1]), "=r"(r[2]), "=r"(r[3]) : "r"(addr));
}
__device__ __forceinline__ void ldsm2(uint32_t* r, uint32_t addr) {
    asm volatile("ldmatrix.sync.aligned.m8n8.x2.shared.b16 {%0,%1}, [%2];"
                 : "=r"(r[0]), "=r"(r[1]) : "r"(addr));
}
// fp16 MMA, fp32 accumulate
__device__ __forceinline__ void mma16816(float* c, const uint32_t* a, const uint32_t* b) {
    asm volatile(
        "mma.sync.aligned.m16n8k16.row.col.f32.f16.f16.f32 "
        "{%0,%1,%2,%3}, {%4,%5,%6,%7}, {%8,%9}, {%0,%1,%2,%3};"
        : "+f"(c[0]), "+f"(c[1]), "+f"(c[2]), "+f"(c[3])
        : "r"(a[0]), "r"(a[1]), "r"(a[2]), "r"(a[3]), "r"(b[0]), "r"(b[1]));
}
__device__ __forceinline__ uint32_t packhf(float a, float b) {
    __half2 t(__float2half(a), __float2half(b));
    return *(uint32_t*)&t;
}

// ---------------------------------------------------------------------------
// split fp32 -> fp16 hi + fp16 lo
// ---------------------------------------------------------------------------
__global__ __launch_bounds__(256) void split_fp16(
    const float* __restrict__ src, __half* __restrict__ hi,
    __half* __restrict__ lo, int n4)
{
    int i = blockIdx.x * 256 + threadIdx.x;
    if (i >= n4) return;
    float4 v = ((const float4*)src)[i];
    __half h0 = __float2half(v.x);
    __half h1 = __float2half(v.y);
    __half h2 = __float2half(v.z);
    __half h3 = __float2half(v.w);
    ((__half2*)hi)[2*i]   = __half2(h0, h1);
    ((__half2*)hi)[2*i+1] = __half2(h2, h3);
    ((__half2*)lo)[2*i] = __half2(
        __float2half(v.x - __half2float(h0)),
        __float2half(v.y - __half2float(h1)));
    ((__half2*)lo)[2*i+1] = __half2(
        __float2half(v.z - __half2float(h2)),
        __float2half(v.w - __half2float(h3)));
}

// ---------------------------------------------------------------------------
// plain fp32 -> fp16 convert (hi only)
// ---------------------------------------------------------------------------
__global__ __launch_bounds__(256) void to_fp16(
    const float* __restrict__ src, __half* __restrict__ hi, int n4)
{
    int i = blockIdx.x * 256 + threadIdx.x;
    if (i >= n4) return;
    float4 v = ((const float4*)src)[i];
    ((__half2*)hi)[2*i]   = __half2(__float2half(v.x), __float2half(v.y));
    ((__half2*)hi)[2*i+1] = __half2(__float2half(v.z), __float2half(v.w));
}

// ---------------------------------------------------------------------------
// pack q_w|k_w|v_w into one [3072,2048] fp16 (hi only)
// ---------------------------------------------------------------------------
__global__ __launch_bounds__(256) void prep_wqkv(
    const float* __restrict__ qw, const float* __restrict__ kw,
    const float* __restrict__ vw, __half* __restrict__ hi)
{
    int i = blockIdx.x * 256 + threadIdx.x;
    if (i >= NQKV * DIM / 4) return;
    int row = i >> 9;
    int c4  = i & 511;
    const float* src;
    if (row < DIM)            src = qw + (size_t)row * DIM;
    else if (row < DIM + 512) src = kw + (size_t)(row - DIM) * DIM;
    else                      src = vw + (size_t)(row - DIM - 512) * DIM;
    float4 v = ((const float4*)src)[c4];
    ((__half2*)hi)[2*i]   = __half2(__float2half(v.x), __float2half(v.y));
    ((__half2*)hi)[2*i+1] = __half2(__float2half(v.z), __float2half(v.w));
}

// ---------------------------------------------------------------------------
// HMMA GEMM (NT), fp16 split, npass in {2,3}:
//   npass=2: C = Ah*Bh + Al*Bh          (B single fp16)
//   npass=3: C = Ah*Bh + Al*Bh + Ah*Bl  (both split)
// 128x128 CTA tile, BK=64, 8 warps, 3-stage prefetch.
// ---------------------------------------------------------------------------
#define GSTAGE 32768
#define GEMM_SMEM (3 * GSTAGE)

__global__ __launch_bounds__(256) void gemm_tc(
    const __half* __restrict__ Ah, const __half* __restrict__ Al,
    const __half* __restrict__ Bh, const __half* __restrict__ Bl,
    float* __restrict__ C, int M, int N, int K, int npass)
{
    extern __shared__ char sm[];
    const uint32_t smem_base = s2u(sm);
    const int tid = threadIdx.x;
    const int wid = tid >> 5, lane = tid & 31;
    const int wm = wid >> 2, wn = wid & 3;
    const int bm = blockIdx.y * 128, bn = blockIdx.x * 128;

    const int kstages = K >> 6;
    const int S = npass * kstages;

    float acc[4][4][4];
#pragma unroll
    for (int i = 0; i < 4; ++i)
#pragma unroll
        for (int j = 0; j < 4; ++j)
#pragma unroll
            for (int t = 0; t < 4; ++t) acc[i][j][t] = 0.f;

    const int l16 = lane & 15;
    uint32_t aOff[4], aMsk[4], bOff[4], bMsk[4];
#pragma unroll
    for (int mt = 0; mt < 4; ++mt) {
        int row = wm * 64 + mt * 16 + l16;
        aOff[mt] = row * 128;
        aMsk[mt] = (row & 7) << 4;
    }
#pragma unroll
    for (int nt = 0; nt < 4; ++nt) {
        int row = wn * 32 + nt * 8 + (l16 & 7);
        bOff[nt] = row * 128;
        bMsk[nt] = (row & 7) << 4;
    }
    const uint32_t kbA = (lane >> 4) * 16;
    const uint32_t kbB = ((l16 >> 3) & 1) * 16;

    auto load_stage = [&](int s) {
        int p = s / kstages;
        int ks = (s - p * kstages) << 6;
        const __half* Ap = (p == 1) ? Al : Ah;
        const __half* Bp = (p == 2) ? Bl : Bh;
        uint32_t abuf = smem_base + (s % 3) * GSTAGE;
        uint32_t bbuf = abuf + 16384;
#pragma unroll
        for (int i = 0; i < 4; ++i) {
            int c = tid + i * 256;
            int row = c >> 3, c16 = c & 7;
            cp_async16(abuf + SWZ(row * 128 + c16 * 16),
                       Ap + (size_t)(bm + row) * K + ks + c16 * 8);
        }
#pragma unroll
        for (int i = 0; i < 4; ++i) {
            int c = tid + i * 256;
            int row = c >> 3, c16 = c & 7;
            cp_async16(bbuf + SWZ(row * 128 + c16 * 16),
                       Bp + (size_t)(bn + row) * K + ks + c16 * 8);
        }
        asm volatile("cp.async.commit_group;");
    };

    load_stage(0);
    load_stage(1);
    for (int s = 0; s < S; ++s) {
        if (s + 2 < S) {
            load_stage(s + 2);
            asm volatile("cp.async.wait_group 2;" ::: "memory");
        } else if (s + 1 < S) {
            asm volatile("cp.async.wait_group 1;" ::: "memory");
        } else {
            asm volatile("cp.async.wait_group 0;" ::: "memory");
        }
        __syncthreads();

        uint32_t abuf = smem_base + (s % 3) * GSTAGE;
        uint32_t bbuf = abuf + 16384;
#pragma unroll
        for (int kk = 0; kk < 4; ++kk) {
            uint32_t af[4][4], bfr[4][2];
            uint32_t ka = kk * 32 + kbA;
            uint32_t kb = kk * 32 + kbB;
#pragma unroll
            for (int mt = 0; mt < 4; ++mt)
                ldsm4(af[mt], abuf + aOff[mt] + (ka ^ aMsk[mt]));
#pragma unroll
            for (int nt = 0; nt < 4; ++nt)
                ldsm2(bfr[nt], bbuf + bOff[nt] + (kb ^ bMsk[nt]));
#pragma unroll
            for (int mt = 0; mt < 4; ++mt)
#pragma unroll
                for (int nt = 0; nt < 4; ++nt)
                    mma16816(acc[mt][nt], af[mt], bfr[nt]);
        }
        __syncthreads();
    }

    const int er = lane >> 2, ec = (lane & 3) * 2;
#pragma unroll
    for (int mt = 0; mt < 4; ++mt) {
#pragma unroll
        for (int nt = 0; nt < 4; ++nt) {
            int r0 = bm + wm * 64 + mt * 16 + er;
            int c0 = bn + wn * 32 + nt * 8 + ec;
            *(float2*)&C[(size_t)r0 * N + c0] =
                make_float2(acc[mt][nt][0], acc[mt][nt][1]);
            *(float2*)&C[(size_t)(r0 + 8) * N + c0] =
                make_float2(acc[mt][nt][2], acc[mt][nt][3]);
        }
    }
}

// ---------------------------------------------------------------------------
// RoPE tables (T x 64)
// ---------------------------------------------------------------------------
__global__ void rope_table_kernel(float* __restrict__ cs, float* __restrict__ sn)
{
    const int t = blockIdx.x, i = threadIdx.x;
    float base = 10000.f;
    if (TLEN > 1024) base = 10000.f * powf((float)TLEN / 1024.f, 128.f / 126.f);
    float l2b = log2f(base);
    float inv = exp2f(-(float)i * (l2b * (1.f / 64.f)));
    float ang = (float)t * inv;
    cs[t * 64 + i] = cosf(ang);
    sn[t * 64 + i] = sinf(ang);
}

// ---------------------------------------------------------------------------
// Fused RMSNorm + RoPE (+v pass-through), 2 vectors per 256-thread block.
// ---------------------------------------------------------------------------
__global__ __launch_bounds__(256) void norm_rope_kernel(
    const float* __restrict__ qkv, const float* __restrict__ q_gain,
    const float* __restrict__ cs, const float* __restrict__ sn,
    __half* __restrict__ qh, __half* __restrict__ ql,
    __half* __restrict__ kh, __half* __restrict__ vh)
{
    const int sub = threadIdx.x >> 7;
    const int vec = blockIdx.x * 2 + sub;
    const int hh = vec % 24;
    const int token = vec / 24;
    const int t = token % TLEN;
    const int tid = threadIdx.x & 127;

    const float* src = qkv + (size_t)token * NQKV;
    size_t off;
    float gain;
    bool isq;

    __shared__ float red[2][4];
    __shared__ float buf[2][DH];

    if (hh < NH) {
        src += hh * DH;
        off = ((size_t)token * NH + hh) * DH;
        gain = q_gain[hh] * (ATTN_SCALE * LOG2E);
        isq = true;
    } else if (hh < NH + NKV) {
        src += DIM + (hh - NH) * DH;
        off = ((size_t)token * NKV + (hh - NH)) * DH;
        gain = 1.f;
        isq = false;
    } else {
        src += DIM + NKV * DH + (hh - NH - NKV) * DH;
        off = ((size_t)token * NKV + (hh - NH - NKV)) * DH;
        vh[off + tid] = __float2half(src[tid]);
        return;
    }

    float xv = src[tid];

    float s = xv * xv;
#pragma unroll
    for (int o = 16; o > 0; o >>= 1)
        s += __shfl_xor_sync(0xffffffffu, s, o);
    if ((tid & 31) == 0) red[sub][tid >> 5] = s;
    __syncthreads();
    float tot = red[sub][0] + red[sub][1] + red[sub][2] + red[sub][3];
    float rn = rsqrtf(tot * (1.f / DH) + EPSF);
    float xn = xv * rn;

    buf[sub][tid] = xn;
    __syncthreads();

    const int i = tid & 63;
    float c  = cs[t * 64 + i];
    float si = sn[t * 64 + i];
    float x1 = buf[sub][i], x2 = buf[sub][i + 64];
    float r = ((tid < 64) ? (x1 * c + x2 * si) : (-x1 * si + x2 * c)) * gain;

    if (isq) {
        __half hv = __float2half(r);
        qh[off + tid] = hv;
        ql[off + tid] = __float2half(r - __half2float(hv));
    } else {
        kh[off + tid] = __float2half(r);
    }
}

// ---------------------------------------------------------------------------
// HMMA flash attention (causal, GQA), fp16 2-term:
//   S = (qh+ql)*Kh ;  O += (ph+pl)*Vh
// smem 64KB -> 3 CTA/SM. (R14-validated)
// ---------------------------------------------------------------------------
#define ATTN_SMEM (4 * 16384)

__global__ __launch_bounds__(128) void attn_mma(
    const __half* __restrict__ qh, const __half* __restrict__ ql,
    const __half* __restrict__ kh, const __half* __restrict__ vh,
    __half* __restrict__ oh, __half* __restrict__ ol)
{
    extern __shared__ char smc[];
    const uint32_t sQH = s2u(smc);
    const uint32_t sQL = sQH + 16384;
    const uint32_t sKH = sQL + 16384;
    const uint32_t sVH = sKH + 16384;

    const int pr = blockIdx.x;
    const int h = blockIdx.y, b = blockIdx.z;
    const int hkv = h >> 2;
    const int tid = threadIdx.x, wid = tid >> 5, lane = tid & 31;
    const int quad = lane >> 2, qx = lane & 3;

    const uint32_t aRow = wid * 16 + (lane & 15);
    const uint32_t aSwz = (aRow & 7) << 4;
    const uint32_t aKb  = (lane >> 4) * 16;
    const uint32_t kRowB = ((lane >> 4) & 1) * 8 + (lane & 7);
    const uint32_t kKb   = ((lane >> 3) & 1) * 16;
    const uint32_t vRowB = ((lane >> 3) & 1) * 8 + (lane & 7);
    const uint32_t vCb   = ((lane >> 4) & 1) * 16;

    for (int sel = 0; sel < 2; ++sel) {
        const int qb = sel ? (NQT - 1 - pr) : pr;
        const int q0 = qb * 64;

        __syncthreads();
        for (int i = tid; i < 1024; i += 128) {
            int row = i >> 4, cb = (i & 15) * 16;
            uint32_t sw = row * 256 + (cb ^ ((row & 7) << 4));
            size_t g = ((size_t)(b * TLEN + q0 + row) * NH + h) * DH + (i & 15) * 8;
            cp_async16(sQH + sw, qh + g);
            cp_async16(sQL + sw, ql + g);
        }
        asm volatile("cp.async.commit_group;");
        asm volatile("cp.async.wait_group 0;" ::: "memory");
        __syncthreads();

        uint32_t qfh[8][4], qfl[8][4];
#pragma unroll
        for (int kk = 0; kk < 8; ++kk) {
            ldsm4(qfh[kk], sQH + aRow * 256 + ((kk * 32 + aKb) ^ aSwz));
            ldsm4(qfl[kk], sQL + aRow * 256 + ((kk * 32 + aKb) ^ aSwz));
        }

        float acc[16][4];
#pragma unroll
        for (int j = 0; j < 16; ++j)
#pragma unroll
            for (int t = 0; t < 4; ++t) acc[j][t] = 0.f;
        float m0 = -1e30f, m1 = -1e30f, l0 = 0.f, l1 = 0.f;

        for (int kt = 0; kt <= qb; ++kt) {
            __syncthreads();
            for (int i = tid; i < 1024; i += 128) {
                int row = i >> 4, cb = (i & 15) * 16;
                uint32_t sw = row * 256 + (cb ^ ((row & 7) << 4));
                size_t g = ((size_t)(b * TLEN + kt * 64 + row) * NKV + hkv) * DH
                           + (i & 15) * 8;
                cp_async16(sKH + sw, kh + g);
                cp_async16(sVH + sw, vh + g);
            }
            asm volatile("cp.async.commit_group;");
            asm volatile("cp.async.wait_group 0;" ::: "memory");
            __syncthreads();

            float s[8][4];
#pragma unroll
            for (int j = 0; j < 8; ++j)
#pragma unroll
                for (int t = 0; t < 4; ++t) s[j][t] = 0.f;

#pragma unroll
            for (int kk = 0; kk < 8; ++kk) {
#pragma unroll
                for (int jj = 0; jj < 4; ++jj) {
                    uint32_t kr = jj * 16 + kRowB;
                    uint32_t off = kr * 256 + ((kk * 32 + kKb) ^ ((kr & 7) << 4));
                    uint32_t kf[4];
                    ldsm4(kf, sKH + off);
                    mma16816(s[2 * jj],     qfh[kk], kf);
                    mma16816(s[2 * jj + 1], qfh[kk], kf + 2);
                    mma16816(s[2 * jj],     qfl[kk], kf);
                    mma16816(s[2 * jj + 1], qfl[kk], kf + 2);
                }
            }

            if (kt == qb) {
                int gr = wid * 16 + quad;
#pragma unroll
                for (int j = 0; j < 8; ++j) {
                    int gc = j * 8 + qx * 2;
                    if (gc     > gr)     s[j][0] = -1e30f;
                    if (gc + 1 > gr)     s[j][1] = -1e30f;
                    if (gc     > gr + 8) s[j][2] = -1e30f;
                    if (gc + 1 > gr + 8) s[j][3] = -1e30f;
                }
            }

            float t0 = -1e30f, t1 = -1e30f;
#pragma unroll
            for (int j = 0; j < 8; ++j) {
                t0 = fmaxf(t0, fmaxf(s[j][0], s[j][1]));
                t1 = fmaxf(t1, fmaxf(s[j][2], s[j][3]));
            }
            t0 = fmaxf(t0, __shfl_xor_sync(0xffffffffu, t0, 1));
            t0 = fmaxf(t0, __shfl_xor_sync(0xffffffffu, t0, 2));
            t1 = fmaxf(t1, __shfl_xor_sync(0xffffffffu, t1, 1));
            t1 = fmaxf(t1, __shfl_xor_sync(0xffffffffu, t1, 2));
            float mn0 = fmaxf(m0, t0), mn1 = fmaxf(m1, t1);
            float sc0 = exp2f(m0 - mn0), sc1 = exp2f(m1 - mn1);
            m0 = mn0; m1 = mn1;

            uint32_t phA[8], phB[8], plA[8], plB[8];
            float ls0 = 0.f, ls1 = 0.f;
#pragma unroll
            for (int j = 0; j < 8; ++j) {
                float p0 = exp2f(s[j][0] - mn0);
                float p1 = exp2f(s[j][1] - mn0);
                float p2 = exp2f(s[j][2] - mn1);
                float p3 = exp2f(s[j][3] - mn1);
                ls0 += p0 + p1; ls1 += p2 + p3;
                __half h0 = __float2half(p0), h1 = __float2half(p1);
                __half h2 = __float2half(p2), h3 = __float2half(p3);
                __half2 a(h0, h1), bb(h2, h3);
                phA[j] = *(uint32_t*)&a; phB[j] = *(uint32_t*)&bb;
                plA[j] = packhf(p0 - __half2float(h0), p1 - __half2float(h1));
                plB[j] = packhf(p2 - __half2float(h2), p3 - __half2float(h3));
            }
            l0 = l0 * sc0 + ls0;
            l1 = l1 * sc1 + ls1;
#pragma unroll
            for (int j = 0; j < 16; ++j) {
                acc[j][0] *= sc0; acc[j][1] *= sc0;
                acc[j][2] *= sc1; acc[j][3] *= sc1;
            }

#pragma unroll
            for (int kk = 0; kk < 4; ++kk) {
                uint32_t aH[4] = {phA[2*kk], phB[2*kk], phA[2*kk+1], phB[2*kk+1]};
                uint32_t aL[4] = {plA[2*kk], plB[2*kk], plA[2*kk+1], plB[2*kk+1]};
                uint32_t vr = kk * 16 + vRowB;
                uint32_t vsw = (vr & 7) << 4;
#pragma unroll
                for (int jp = 0; jp < 8; ++jp) {
                    uint32_t off = vr * 256 + ((jp * 32 + vCb) ^ vsw);
                    uint32_t vf[4];
                    ldsm4t(vf, sVH + off);
                    mma16816(acc[2 * jp],     aH, vf);
                    mma16816(acc[2 * jp + 1], aH, vf + 2);
                    mma16816(acc[2 * jp],     aL, vf);
                    mma16816(acc[2 * jp + 1], aL, vf + 2);
                }
            }
        }

        l0 += __shfl_xor_sync(0xffffffffu, l0, 1);
        l0 += __shfl_xor_sync(0xffffffffu, l0, 2);
        l1 += __shfl_xor_sync(0xffffffffu, l1, 1);
        l1 += __shfl_xor_sync(0xffffffffu, l1, 2);
        float i0 = 1.f / l0, i1 = 1.f / l1;

        size_t tok0 = (size_t)(b * TLEN + q0 + wid * 16 + quad);
        size_t tok1 = tok0 + 8;
#pragma unroll
        for (int j = 0; j < 16; ++j) {
            int col = h * DH + j * 8 + qx * 2;
            float v0 = acc[j][0] * i0, v1 = acc[j][1] * i0;
            float v2 = acc[j][2] * i1, v3 = acc[j][3] * i1;
            __half h0 = __float2half(v0), h1 = __float2half(v1);
            __half h2 = __float2half(v2), h3 = __float2half(v3);
            *(__half2*)&oh[tok0 * DIM + col] = __half2(h0, h1);
            *(__half2*)&oh[tok1 * DIM + col] = __half2(h2, h3);
            *(__half2*)&ol[tok0 * DIM + col] =
                __half2(__float2half(v0 - __half2float(h0)),
                        __float2half(v1 - __half2float(h1)));
            *(__half2*)&ol[tok1 * DIM + col] =
                __half2(__float2half(v2 - __half2float(h2)),
                        __float2half(v3 - __half2float(h3)));
        }
    }
}

// ---------------------------------------------------------------------------
extern "C" void kernel_launch(void* const* d_in, const int* in_sizes, int n_in,
                              void* d_out, int out_size)
{
    const float* x  = (const float*)d_in[0];
    const float* qw = (const float*)d_in[1];
    const float* kw = (const float*)d_in[2];
    const float* vw = (const float*)d_in[3];
    const float* ow = (const float*)d_in[4];
    const float* qg = (const float*)d_in[5];
    float* out = (float*)d_out;

    float *gqkv, *gcos, *gsin;
    cudaGetSymbolAddress((void**)&gqkv, g_qkv);
    cudaGetSymbolAddress((void**)&gcos, g_cos);
    cudaGetSymbolAddress((void**)&gsin, g_sin);

    __half *xh, *xl, *wqh, *owh, *oh, *ol;
    __half *qbh, *qbl, *kbh, *vbh;
    cudaGetSymbolAddress((void**)&xh,  g_xh);    cudaGetSymbolAddress((void**)&xl,  g_xl);
    cudaGetSymbolAddress((void**)&wqh, g_wqkvh);
    cudaGetSymbolAddress((void**)&owh, g_owh);
    cudaGetSymbolAddress((void**)&oh,  g_oh);    cudaGetSymbolAddress((void**)&ol,  g_ol);
    cudaGetSymbolAddress((void**)&qbh, g_qbh);   cudaGetSymbolAddress((void**)&qbl, g_qbl);
    cudaGetSymbolAddress((void**)&kbh, g_kbh);   cudaGetSymbolAddress((void**)&vbh, g_vbh);

    const int M = MTOT, K = DIM;

    cudaFuncSetAttribute(gemm_tc, cudaFuncAttributeMaxDynamicSharedMemorySize, GEMM_SMEM);
    cudaFuncSetAttribute(attn_mma, cudaFuncAttributeMaxDynamicSharedMemorySize, ATTN_SMEM);

    rope_table_kernel<<<TLEN, 64>>>(gcos, gsin);                           // 0
    split_fp16<<<(M*K/4 + 255)/256, 256>>>(x, xh, xl, M*K/4);              // 1
    prep_wqkv<<<(NQKV*DIM/4 + 255)/256, 256>>>(qw, kw, vw, wqh);           // 2
    gemm_tc<<<dim3(NQKV/128, M/128), 256, GEMM_SMEM>>>(                     // 3
        xh, xl, wqh, wqh, gqkv, M, NQKV, K, 2);
    norm_rope_kernel<<<M * 12, 256>>>(gqkv, qg, gcos, gsin,                // 4
                                      qbh, qbl, kbh, vbh);
    attn_mma<<<dim3(NQT/2, NH, BATCH), 128, ATTN_SMEM>>>(                   // 5
        qbh, qbl, kbh, vbh, oh, ol);
    to_fp16<<<(DIM*DIM/4 + 255)/256, 256>>>(ow, owh, DIM*DIM/4);           // 6
    gemm_tc<<<dim3(DIM/128, M/128), 256, GEMM_SMEM>>>(                      // 7
        oh, ol, owh, owh, out, M, DIM, K, 2);
}

// round 16
// speedup vs baseline: 1.4791x; 1.0572x over previous
#include <cuda_runtime.h>
#include <cuda_fp16.h>
#include <math.h>
#include <stdint.h>

// Problem constants (fixed: B=2, T=2048, DIM=2048, H=16, HKV=4, D=128)
#define BATCH 2
#define TLEN  2048
#define DIM   2048
#define NH    16
#define NKV   4
#define DH    128
#define MTOT  (BATCH * TLEN)
#define NQKV  (DIM + 2 * NKV * DH)     // 3072 packed output cols
#define NQT   (TLEN / 64)              // 32 query tiles
#define ATTN_SCALE 0.08838834764831845f
#define LOG2E 1.4426950408889634f
#define EPSF 1.1920929e-07f

// ---------------- scratch (device globals) ---------------------------------
__device__ float g_qkv[MTOT * NQKV];   // packed q|k|v fp32

__device__ __half g_xh[MTOT * DIM],  g_xl[MTOT * DIM];
__device__ __half g_wqkvh[NQKV * DIM];                 // weights: hi only
__device__ __half g_owh[DIM * DIM];                    // out-proj W: hi only
__device__ __half g_oh[MTOT * DIM],  g_ol[MTOT * DIM];

__device__ __half g_qbh[MTOT * DIM], g_qbl[MTOT * DIM];
__device__ __half g_kbh[MTOT * NKV * DH];              // K: hi only
__device__ __half g_vbh[MTOT * NKV * DH];              // V: hi only

__device__ float g_cos[TLEN * 64];
__device__ float g_sin[TLEN * 64];

// ---------------------------------------------------------------------------
__device__ __forceinline__ uint32_t s2u(const void* p) {
    return (uint32_t)__cvta_generic_to_shared(p);
}
#define SWZ(o) ((o) ^ (((o) >> 3) & 0x70))

__device__ __forceinline__ void cp_async16(uint32_t saddr, const void* gaddr) {
    asm volatile("cp.async.cg.shared.global [%0], [%1], 16;\n"
                 :: "r"(saddr), "l"(gaddr));
}
__device__ __forceinline__ void ldsm4(uint32_t* r, uint32_t addr) {
    asm volatile("ldmatrix.sync.aligned.m8n8.x4.shared.b16 {%0,%1,%2,%3}, [%4];"
                 : "=r"(r[0]), "=r"(r[1]), "=r"(r[2]), "=r"(r[3]) : "r"(addr));
}
__device__ __forceinline__ void ldsm4t(uint32_t* r, uint32_t addr) {
    asm volatile("ldmatrix.sync.aligned.m8n8.x4.trans.shared.b16 {%0,%1,%2,%3}, [%4];"
                 : "=r"(r[0]), "=r"(r[1]), "=r"(r[2]), "=r"(r[3]) : "r"(addr));
}
__device__ __forceinline__ void ldsm2(uint32_t* r, uint32_t addr) {
    asm volatile("ldmatrix.sync.aligned.m8n8.x2.shared.b16 {%0,%1}, [%2];"
                 : "=r"(r[0]), "=r"(r[1]) : "r"(addr));
}
// fp16 MMA, fp32 accumulate
__device__ __forceinline__ void mma16816(float* c, const uint32_t* a, const uint32_t* b) {
    asm volatile(
        "mma.sync.aligned.m16n8k16.row.col.f32.f16.f16.f32 "
        "{%0,%1,%2,%3}, {%4,%5,%6,%7}, {%8,%9}, {%0,%1,%2,%3};"
        : "+f"(c[0]), "+f"(c[1]), "+f"(c[2]), "+f"(c[3])
        : "r"(a[0]), "r"(a[1]), "r"(a[2]), "r"(a[3]), "r"(b[0]), "r"(b[1]));
}
__device__ __forceinline__ uint32_t packhf(float a, float b) {
    __half2 t(__float2half(a), __float2half(b));
    return *(uint32_t*)&t;
}

// ---------------------------------------------------------------------------
// split fp32 -> fp16 hi + fp16 lo
// ---------------------------------------------------------------------------
__global__ __launch_bounds__(256) void split_fp16(
    const float* __restrict__ src, __half* __restrict__ hi,
    __half* __restrict__ lo, int n4)
{
    int i = blockIdx.x * 256 + threadIdx.x;
    if (i >= n4) return;
    float4 v = ((const float4*)src)[i];
    __half h0 = __float2half(v.x);
    __half h1 = __float2half(v.y);
    __half h2 = __float2half(v.z);
    __half h3 = __float2half(v.w);
    ((__half2*)hi)[2*i]   = __half2(h0, h1);
    ((__half2*)hi)[2*i+1] = __half2(h2, h3);
    ((__half2*)lo)[2*i] = __half2(
        __float2half(v.x - __half2float(h0)),
        __float2half(v.y - __half2float(h1)));
    ((__half2*)lo)[2*i+1] = __half2(
        __float2half(v.z - __half2float(h2)),
        __float2half(v.w - __half2float(h3)));
}

// ---------------------------------------------------------------------------
// plain fp32 -> fp16 convert (hi only)
// ---------------------------------------------------------------------------
__global__ __launch_bounds__(256) void to_fp16(
    const float* __restrict__ src, __half* __restrict__ hi, int n4)
{
    int i = blockIdx.x * 256 + threadIdx.x;
    if (i >= n4) return;
    float4 v = ((const float4*)src)[i];
    ((__half2*)hi)[2*i]   = __half2(__float2half(v.x), __float2half(v.y));
    ((__half2*)hi)[2*i+1] = __half2(__float2half(v.z), __float2half(v.w));
}

// ---------------------------------------------------------------------------
// pack q_w|k_w|v_w into one [3072,2048] fp16 (hi only)
// ---------------------------------------------------------------------------
__global__ __launch_bounds__(256) void prep_wqkv(
    const float* __restrict__ qw, const float* __restrict__ kw,
    const float* __restrict__ vw, __half* __restrict__ hi)
{
    int i = blockIdx.x * 256 + threadIdx.x;
    if (i >= NQKV * DIM / 4) return;
    int row = i >> 9;
    int c4  = i & 511;
    const float* src;
    if (row < DIM)            src = qw + (size_t)row * DIM;
    else if (row < DIM + 512) src = kw + (size_t)(row - DIM) * DIM;
    else                      src = vw + (size_t)(row - DIM - 512) * DIM;
    float4 v = ((const float4*)src)[c4];
    ((__half2*)hi)[2*i]   = __half2(__float2half(v.x), __float2half(v.y));
    ((__half2*)hi)[2*i+1] = __half2(__float2half(v.z), __float2half(v.w));
}

// ---------------------------------------------------------------------------
// HMMA GEMM (NT), fp16 split. Pass 2 (Al*Bh) only for columns bn < n2
// (K/V columns feed single-fp16 consumers, so the refinement is wasted there).
// 128x128 CTA tile, BK=64, 8 warps, 3-stage prefetch.
// ---------------------------------------------------------------------------
#define GSTAGE 32768
#define GEMM_SMEM (3 * GSTAGE)

__global__ __launch_bounds__(256) void gemm_tc(
    const __half* __restrict__ Ah, const __half* __restrict__ Al,
    const __half* __restrict__ Bh,
    float* __restrict__ C, int M, int N, int K, int n2)
{
    extern __shared__ char sm[];
    const uint32_t smem_base = s2u(sm);
    const int tid = threadIdx.x;
    const int wid = tid >> 5, lane = tid & 31;
    const int wm = wid >> 2, wn = wid & 3;
    const int bm = blockIdx.y * 128, bn = blockIdx.x * 128;

    const int kstages = K >> 6;
    const int S = (bn < n2 ? 2 : 1) * kstages;

    float acc[4][4][4];
#pragma unroll
    for (int i = 0; i < 4; ++i)
#pragma unroll
        for (int j = 0; j < 4; ++j)
#pragma unroll
            for (int t = 0; t < 4; ++t) acc[i][j][t] = 0.f;

    const int l16 = lane & 15;
    uint32_t aOff[4], aMsk[4], bOff[4], bMsk[4];
#pragma unroll
    for (int mt = 0; mt < 4; ++mt) {
        int row = wm * 64 + mt * 16 + l16;
        aOff[mt] = row * 128;
        aMsk[mt] = (row & 7) << 4;
    }
#pragma unroll
    for (int nt = 0; nt < 4; ++nt) {
        int row = wn * 32 + nt * 8 + (l16 & 7);
        bOff[nt] = row * 128;
        bMsk[nt] = (row & 7) << 4;
    }
    const uint32_t kbA = (lane >> 4) * 16;
    const uint32_t kbB = ((l16 >> 3) & 1) * 16;

    auto load_stage = [&](int s) {
        int p = s / kstages;
        int ks = (s - p * kstages) << 6;
        const __half* Ap = (p == 1) ? Al : Ah;
        uint32_t abuf = smem_base + (s % 3) * GSTAGE;
        uint32_t bbuf = abuf + 16384;
#pragma unroll
        for (int i = 0; i < 4; ++i) {
            int c = tid + i * 256;
            int row = c >> 3, c16 = c & 7;
            cp_async16(abuf + SWZ(row * 128 + c16 * 16),
                       Ap + (size_t)(bm + row) * K + ks + c16 * 8);
        }
#pragma unroll
        for (int i = 0; i < 4; ++i) {
            int c = tid + i * 256;
            int row = c >> 3, c16 = c & 7;
            cp_async16(bbuf + SWZ(row * 128 + c16 * 16),
                       Bh + (size_t)(bn + row) * K + ks + c16 * 8);
        }
        asm volatile("cp.async.commit_group;");
    };

    load_stage(0);
    load_stage(1);
    for (int s = 0; s < S; ++s) {
        if (s + 2 < S) {
            load_stage(s + 2);
            asm volatile("cp.async.wait_group 2;" ::: "memory");
        } else if (s + 1 < S) {
            asm volatile("cp.async.wait_group 1;" ::: "memory");
        } else {
            asm volatile("cp.async.wait_group 0;" ::: "memory");
        }
        __syncthreads();

        uint32_t abuf = smem_base + (s % 3) * GSTAGE;
        uint32_t bbuf = abuf + 16384;
#pragma unroll
        for (int kk = 0; kk < 4; ++kk) {
            uint32_t af[4][4], bfr[4][2];
            uint32_t ka = kk * 32 + kbA;
            uint32_t kb = kk * 32 + kbB;
#pragma unroll
            for (int mt = 0; mt < 4; ++mt)
                ldsm4(af[mt], abuf + aOff[mt] + (ka ^ aMsk[mt]));
#pragma unroll
            for (int nt = 0; nt < 4; ++nt)
                ldsm2(bfr[nt], bbuf + bOff[nt] + (kb ^ bMsk[nt]));
#pragma unroll
            for (int mt = 0; mt < 4; ++mt)
#pragma unroll
                for (int nt = 0; nt < 4; ++nt)
                    mma16816(acc[mt][nt], af[mt], bfr[nt]);
        }
        __syncthreads();
    }

    const int er = lane >> 2, ec = (lane & 3) * 2;
#pragma unroll
    for (int mt = 0; mt < 4; ++mt) {
#pragma unroll
        for (int nt = 0; nt < 4; ++nt) {
            int r0 = bm + wm * 64 + mt * 16 + er;
            int c0 = bn + wn * 32 + nt * 8 + ec;
            *(float2*)&C[(size_t)r0 * N + c0] =
                make_float2(acc[mt][nt][0], acc[mt][nt][1]);
            *(float2*)&C[(size_t)(r0 + 8) * N + c0] =
                make_float2(acc[mt][nt][2], acc[mt][nt][3]);
        }
    }
}

// ---------------------------------------------------------------------------
// RoPE tables (T x 64)
// ---------------------------------------------------------------------------
__global__ void rope_table_kernel(float* __restrict__ cs, float* __restrict__ sn)
{
    const int t = blockIdx.x, i = threadIdx.x;
    float base = 10000.f;
    if (TLEN > 1024) base = 10000.f * powf((float)TLEN / 1024.f, 128.f / 126.f);
    float l2b = log2f(base);
    float inv = exp2f(-(float)i * (l2b * (1.f / 64.f)));
    float ang = (float)t * inv;
    cs[t * 64 + i] = cosf(ang);
    sn[t * 64 + i] = sinf(ang);
}

// ---------------------------------------------------------------------------
// Fused RMSNorm + RoPE (+v pass-through), 2 vectors per 256-thread block.
// ---------------------------------------------------------------------------
__global__ __launch_bounds__(256) void norm_rope_kernel(
    const float* __restrict__ qkv, const float* __restrict__ q_gain,
    const float* __restrict__ cs, const float* __restrict__ sn,
    __half* __restrict__ qh, __half* __restrict__ ql,
    __half* __restrict__ kh, __half* __restrict__ vh)
{
    const int sub = threadIdx.x >> 7;
    const int vec = blockIdx.x * 2 + sub;
    const int hh = vec % 24;
    const int token = vec / 24;
    const int t = token % TLEN;
    const int tid = threadIdx.x & 127;

    const float* src = qkv + (size_t)token * NQKV;
    size_t off;
    float gain;
    bool isq;

    __shared__ float red[2][4];
    __shared__ float buf[2][DH];

    if (hh < NH) {
        src += hh * DH;
        off = ((size_t)token * NH + hh) * DH;
        gain = q_gain[hh] * (ATTN_SCALE * LOG2E);
        isq = true;
    } else if (hh < NH + NKV) {
        src += DIM + (hh - NH) * DH;
        off = ((size_t)token * NKV + (hh - NH)) * DH;
        gain = 1.f;
        isq = false;
    } else {
        src += DIM + NKV * DH + (hh - NH - NKV) * DH;
        off = ((size_t)token * NKV + (hh - NH - NKV)) * DH;
        vh[off + tid] = __float2half(src[tid]);
        return;
    }

    float xv = src[tid];

    float s = xv * xv;
#pragma unroll
    for (int o = 16; o > 0; o >>= 1)
        s += __shfl_xor_sync(0xffffffffu, s, o);
    if ((tid & 31) == 0) red[sub][tid >> 5] = s;
    __syncthreads();
    float tot = red[sub][0] + red[sub][1] + red[sub][2] + red[sub][3];
    float rn = rsqrtf(tot * (1.f / DH) + EPSF);
    float xn = xv * rn;

    buf[sub][tid] = xn;
    __syncthreads();

    const int i = tid & 63;
    float c  = cs[t * 64 + i];
    float si = sn[t * 64 + i];
    float x1 = buf[sub][i], x2 = buf[sub][i + 64];
    float r = ((tid < 64) ? (x1 * c + x2 * si) : (-x1 * si + x2 * c)) * gain;

    if (isq) {
        __half hv = __float2half(r);
        qh[off + tid] = hv;
        ql[off + tid] = __float2half(r - __half2float(hv));
    } else {
        kh[off + tid] = __float2half(r);
    }
}

// ---------------------------------------------------------------------------
// HMMA flash attention (causal, GQA), fp16 2-term.
// R16: one q-block per CTA, launched LARGEST-FIRST (qb = 31 - bid.x) so LPT
// scheduling packs the 1024 variable-work CTAs into 444 slots efficiently.
// ---------------------------------------------------------------------------
#define ATTN_SMEM (4 * 16384)

__global__ __launch_bounds__(128) void attn_mma(
    const __half* __restrict__ qh, const __half* __restrict__ ql,
    const __half* __restrict__ kh, const __half* __restrict__ vh,
    __half* __restrict__ oh, __half* __restrict__ ol)
{
    extern __shared__ char smc[];
    const uint32_t sQH = s2u(smc);
    const uint32_t sQL = sQH + 16384;
    const uint32_t sKH = sQL + 16384;
    const uint32_t sVH = sKH + 16384;

    const int qb = NQT - 1 - blockIdx.x;   // largest work first
    const int h = blockIdx.y, b = blockIdx.z;
    const int hkv = h >> 2;
    const int tid = threadIdx.x, wid = tid >> 5, lane = tid & 31;
    const int quad = lane >> 2, qx = lane & 3;
    const int q0 = qb * 64;

    const uint32_t aRow = wid * 16 + (lane & 15);
    const uint32_t aSwz = (aRow & 7) << 4;
    const uint32_t aKb  = (lane >> 4) * 16;
    const uint32_t kRowB = ((lane >> 4) & 1) * 8 + (lane & 7);
    const uint32_t kKb   = ((lane >> 3) & 1) * 16;
    const uint32_t vRowB = ((lane >> 3) & 1) * 8 + (lane & 7);
    const uint32_t vCb   = ((lane >> 4) & 1) * 16;

    for (int i = tid; i < 1024; i += 128) {
        int row = i >> 4, cb = (i & 15) * 16;
        uint32_t sw = row * 256 + (cb ^ ((row & 7) << 4));
        size_t g = ((size_t)(b * TLEN + q0 + row) * NH + h) * DH + (i & 15) * 8;
        cp_async16(sQH + sw, qh + g);
        cp_async16(sQL + sw, ql + g);
    }
    asm volatile("cp.async.commit_group;");
    asm volatile("cp.async.wait_group 0;" ::: "memory");
    __syncthreads();

    uint32_t qfh[8][4], qfl[8][4];
#pragma unroll
    for (int kk = 0; kk < 8; ++kk) {
        ldsm4(qfh[kk], sQH + aRow * 256 + ((kk * 32 + aKb) ^ aSwz));
        ldsm4(qfl[kk], sQL + aRow * 256 + ((kk * 32 + aKb) ^ aSwz));
    }

    float acc[16][4];
#pragma unroll
    for (int j = 0; j < 16; ++j)
#pragma unroll
        for (int t = 0; t < 4; ++t) acc[j][t] = 0.f;
    float m0 = -1e30f, m1 = -1e30f, l0 = 0.f, l1 = 0.f;

    for (int kt = 0; kt <= qb; ++kt) {
        __syncthreads();
        for (int i = tid; i < 1024; i += 128) {
            int row = i >> 4, cb = (i & 15) * 16;
            uint32_t sw = row * 256 + (cb ^ ((row & 7) << 4));
            size_t g = ((size_t)(b * TLEN + kt * 64 + row) * NKV + hkv) * DH
                       + (i & 15) * 8;
            cp_async16(sKH + sw, kh + g);
            cp_async16(sVH + sw, vh + g);
        }
        asm volatile("cp.async.commit_group;");
        asm volatile("cp.async.wait_group 0;" ::: "memory");
        __syncthreads();

        float s[8][4];
#pragma unroll
        for (int j = 0; j < 8; ++j)
#pragma unroll
            for (int t = 0; t < 4; ++t) s[j][t] = 0.f;

#pragma unroll
        for (int kk = 0; kk < 8; ++kk) {
#pragma unroll
            for (int jj = 0; jj < 4; ++jj) {
                uint32_t kr = jj * 16 + kRowB;
                uint32_t off = kr * 256 + ((kk * 32 + kKb) ^ ((kr & 7) << 4));
                uint32_t kf[4];
                ldsm4(kf, sKH + off);
                mma16816(s[2 * jj],     qfh[kk], kf);
                mma16816(s[2 * jj + 1], qfh[kk], kf + 2);
                mma16816(s[2 * jj],     qfl[kk], kf);
                mma16816(s[2 * jj + 1], qfl[kk], kf + 2);
            }
        }

        if (kt == qb) {
            int gr = wid * 16 + quad;
#pragma unroll
            for (int j = 0; j < 8; ++j) {
                int gc = j * 8 + qx * 2;
                if (gc     > gr)     s[j][0] = -1e30f;
                if (gc + 1 > gr)     s[j][1] = -1e30f;
                if (gc     > gr + 8) s[j][2] = -1e30f;
                if (gc + 1 > gr + 8) s[j][3] = -1e30f;
            }
        }

        float t0 = -1e30f, t1 = -1e30f;
#pragma unroll
        for (int j = 0; j < 8; ++j) {
            t0 = fmaxf(t0, fmaxf(s[j][0], s[j][1]));
            t1 = fmaxf(t1, fmaxf(s[j][2], s[j][3]));
        }
        t0 = fmaxf(t0, __shfl_xor_sync(0xffffffffu, t0, 1));
        t0 = fmaxf(t0, __shfl_xor_sync(0xffffffffu, t0, 2));
        t1 = fmaxf(t1, __shfl_xor_sync(0xffffffffu, t1, 1));
        t1 = fmaxf(t1, __shfl_xor_sync(0xffffffffu, t1, 2));
        float mn0 = fmaxf(m0, t0), mn1 = fmaxf(m1, t1);
        float sc0 = exp2f(m0 - mn0), sc1 = exp2f(m1 - mn1);
        m0 = mn0; m1 = mn1;

        uint32_t phA[8], phB[8], plA[8], plB[8];
        float ls0 = 0.f, ls1 = 0.f;
#pragma unroll
        for (int j = 0; j < 8; ++j) {
            float p0 = exp2f(s[j][0] - mn0);
            float p1 = exp2f(s[j][1] - mn0);
            float p2 = exp2f(s[j][2] - mn1);
            float p3 = exp2f(s[j][3] - mn1);
            ls0 += p0 + p1; ls1 += p2 + p3;
            __half h0 = __float2half(p0), h1 = __float2half(p1);
            __half h2 = __float2half(p2), h3 = __float2half(p3);
            __half2 a(h0, h1), bb(h2, h3);
            phA[j] = *(uint32_t*)&a; phB[j] = *(uint32_t*)&bb;
            plA[j] = packhf(p0 - __half2float(h0), p1 - __half2float(h1));
            plB[j] = packhf(p2 - __half2float(h2), p3 - __half2float(h3));
        }
        l0 = l0 * sc0 + ls0;
        l1 = l1 * sc1 + ls1;
#pragma unroll
        for (int j = 0; j < 16; ++j) {
            acc[j][0] *= sc0; acc[j][1] *= sc0;
            acc[j][2] *= sc1; acc[j][3] *= sc1;
        }

#pragma unroll
        for (int kk = 0; kk < 4; ++kk) {
            uint32_t aH[4] = {phA[2*kk], phB[2*kk], phA[2*kk+1], phB[2*kk+1]};
            uint32_t aL[4] = {plA[2*kk], plB[2*kk], plA[2*kk+1], plB[2*kk+1]};
            uint32_t vr = kk * 16 + vRowB;
            uint32_t vsw = (vr & 7) << 4;
#pragma unroll
            for (int jp = 0; jp < 8; ++jp) {
                uint32_t off = vr * 256 + ((jp * 32 + vCb) ^ vsw);
                uint32_t vf[4];
                ldsm4t(vf, sVH + off);
                mma16816(acc[2 * jp],     aH, vf);
                mma16816(acc[2 * jp + 1], aH, vf + 2);
                mma16816(acc[2 * jp],     aL, vf);
                mma16816(acc[2 * jp + 1], aL, vf + 2);
            }
        }
    }

    l0 += __shfl_xor_sync(0xffffffffu, l0, 1);
    l0 += __shfl_xor_sync(0xffffffffu, l0, 2);
    l1 += __shfl_xor_sync(0xffffffffu, l1, 1);
    l1 += __shfl_xor_sync(0xffffffffu, l1, 2);
    float i0 = 1.f / l0, i1 = 1.f / l1;

    size_t tok0 = (size_t)(b * TLEN + q0 + wid * 16 + quad);
    size_t tok1 = tok0 + 8;
#pragma unroll
    for (int j = 0; j < 16; ++j) {
        int col = h * DH + j * 8 + qx * 2;
        float v0 = acc[j][0] * i0, v1 = acc[j][1] * i0;
        float v2 = acc[j][2] * i1, v3 = acc[j][3] * i1;
        __half h0 = __float2half(v0), h1 = __float2half(v1);
        __half h2 = __float2half(v2), h3 = __float2half(v3);
        *(__half2*)&oh[tok0 * DIM + col] = __half2(h0, h1);
        *(__half2*)&oh[tok1 * DIM + col] = __half2(h2, h3);
        *(__half2*)&ol[tok0 * DIM + col] =
            __half2(__float2half(v0 - __half2float(h0)),
                    __float2half(v1 - __half2float(h1)));
        *(__half2*)&ol[tok1 * DIM + col] =
            __half2(__float2half(v2 - __half2float(h2)),
                    __float2half(v3 - __half2float(h3)));
    }
}

// ---------------------------------------------------------------------------
extern "C" void kernel_launch(void* const* d_in, const int* in_sizes, int n_in,
                              void* d_out, int out_size)
{
    const float* x  = (const float*)d_in[0];
    const float* qw = (const float*)d_in[1];
    const float* kw = (const float*)d_in[2];
    const float* vw = (const float*)d_in[3];
    const float* ow = (const float*)d_in[4];
    const float* qg = (const float*)d_in[5];
    float* out = (float*)d_out;

    float *gqkv, *gcos, *gsin;
    cudaGetSymbolAddress((void**)&gqkv, g_qkv);
    cudaGetSymbolAddress((void**)&gcos, g_cos);
    cudaGetSymbolAddress((void**)&gsin, g_sin);

    __half *xh, *xl, *wqh, *owh, *oh, *ol;
    __half *qbh, *qbl, *kbh, *vbh;
    cudaGetSymbolAddress((void**)&xh,  g_xh);    cudaGetSymbolAddress((void**)&xl,  g_xl);
    cudaGetSymbolAddress((void**)&wqh, g_wqkvh);
    cudaGetSymbolAddress((void**)&owh, g_owh);
    cudaGetSymbolAddress((void**)&oh,  g_oh);    cudaGetSymbolAddress((void**)&ol,  g_ol);
    cudaGetSymbolAddress((void**)&qbh, g_qbh);   cudaGetSymbolAddress((void**)&qbl, g_qbl);
    cudaGetSymbolAddress((void**)&kbh, g_kbh);   cudaGetSymbolAddress((void**)&vbh, g_vbh);

    const int M = MTOT, K = DIM;

    cudaFuncSetAttribute(gemm_tc, cudaFuncAttributeMaxDynamicSharedMemorySize, GEMM_SMEM);
    cudaFuncSetAttribute(attn_mma, cudaFuncAttributeMaxDynamicSharedMemorySize, ATTN_SMEM);

    rope_table_kernel<<<TLEN, 64>>>(gcos, gsin);                           // 0
    split_fp16<<<(M*K/4 + 255)/256, 256>>>(x, xh, xl, M*K/4);              // 1
    prep_wqkv<<<(NQKV*DIM/4 + 255)/256, 256>>>(qw, kw, vw, wqh);           // 2
    gemm_tc<<<dim3(NQKV/128, M/128), 256, GEMM_SMEM>>>(                     // 3
        xh, xl, wqh, gqkv, M, NQKV, K, DIM);        // pass2 for q cols only
    norm_rope_kernel<<<M * 12, 256>>>(gqkv, qg, gcos, gsin,                // 4
                                      qbh, qbl, kbh, vbh);
    attn_mma<<<dim3(NQT, NH, BATCH), 128, ATTN_SMEM>>>(                     // 5
        qbh, qbl, kbh, vbh, oh, ol);
    to_fp16<<<(DIM*DIM/4 + 255)/256, 256>>>(ow, owh, DIM*DIM/4);           // 6
    gemm_tc<<<dim3(DIM/128, M/128), 256, GEMM_SMEM>>>(                      // 7
        oh, ol, owh, out, M, DIM, K, DIM);          // pass2 for all cols
}

// round 17
// speedup vs baseline: 1.6406x; 1.1092x over previous
#include <cuda_runtime.h>
#include <cuda_fp16.h>
#include <math.h>
#include <stdint.h>

// Problem constants (fixed: B=2, T=2048, DIM=2048, H=16, HKV=4, D=128)
#define BATCH 2
#define TLEN  2048
#define DIM   2048
#define NH    16
#define NKV   4
#define DH    128
#define MTOT  (BATCH * TLEN)
#define NQKV  (DIM + 2 * NKV * DH)     // 3072 packed output cols
#define NQT   (TLEN / 64)              // 32 query tiles
#define ATTN_SCALE 0.08838834764831845f
#define LOG2E 1.4426950408889634f
#define EPSF 1.1920929e-07f

// ---------------- scratch (device globals) ---------------------------------
__device__ float g_qkv[MTOT * NQKV];   // packed q|k|v fp32

__device__ __half g_xh[MTOT * DIM],  g_xl[MTOT * DIM];
__device__ __half g_wqkvh[NQKV * DIM];                 // weights: hi only
__device__ __half g_owh[DIM * DIM];                    // out-proj W: hi only
__device__ __half g_oh[MTOT * DIM],  g_ol[MTOT * DIM];

__device__ __half g_qbh[MTOT * DIM], g_qbl[MTOT * DIM];
__device__ __half g_kbh[MTOT * NKV * DH];              // K: hi only
__device__ __half g_vbh[MTOT * NKV * DH];              // V: hi only

__device__ float g_cos[TLEN * 64];
__device__ float g_sin[TLEN * 64];

// ---------------------------------------------------------------------------
__device__ __forceinline__ uint32_t s2u(const void* p) {
    return (uint32_t)__cvta_generic_to_shared(p);
}
#define SWZ(o) ((o) ^ (((o) >> 3) & 0x70))

__device__ __forceinline__ void cp_async16(uint32_t saddr, const void* gaddr) {
    asm volatile("cp.async.cg.shared.global [%0], [%1], 16;\n"
                 :: "r"(saddr), "l"(gaddr));
}
__device__ __forceinline__ void ldsm4(uint32_t* r, uint32_t addr) {
    asm volatile("ldmatrix.sync.aligned.m8n8.x4.shared.b16 {%0,%1,%2,%3}, [%4];"
                 : "=r"(r[0]), "=r"(r[1]), "=r"(r[2]), "=r"(r[3]) : "r"(addr));
}
__device__ __forceinline__ void ldsm4t(uint32_t* r, uint32_t addr) {
    asm volatile("ldmatrix.sync.aligned.m8n8.x4.trans.shared.b16 {%0,%1,%2,%3}, [%4];"
                 : "=r"(r[0]), "=r"(r[1]), "=r"(r[2]), "=r"(r[3]) : "r"(addr));
}
__device__ __forceinline__ void ldsm2(uint32_t* r, uint32_t addr) {
    asm volatile("ldmatrix.sync.aligned.m8n8.x2.shared.b16 {%0,%1}, [%2];"
                 : "=r"(r[0]), "=r"(r[1]) : "r"(addr));
}
// fp16 MMA, fp32 accumulate
__device__ __forceinline__ void mma16816(float* c, const uint32_t* a, const uint32_t* b) {
    asm volatile(
        "mma.sync.aligned.m16n8k16.row.col.f32.f16.f16.f32 "
        "{%0,%1,%2,%3}, {%4,%5,%6,%7}, {%8,%9}, {%0,%1,%2,%3};"
        : "+f"(c[0]), "+f"(c[1]), "+f"(c[2]), "+f"(c[3])
        : "r"(a[0]), "r"(a[1]), "r"(a[2]), "r"(a[3]), "r"(b[0]), "r"(b[1]));
}

// ---------------------------------------------------------------------------
// split fp32 -> fp16 hi + fp16 lo
// ---------------------------------------------------------------------------
__global__ __launch_bounds__(256) void split_fp16(
    const float* __restrict__ src, __half* __restrict__ hi,
    __half* __restrict__ lo, int n4)
{
    int i = blockIdx.x * 256 + threadIdx.x;
    if (i >= n4) return;
    float4 v = ((const float4*)src)[i];
    __half h0 = __float2half(v.x);
    __half h1 = __float2half(v.y);
    __half h2 = __float2half(v.z);
    __half h3 = __float2half(v.w);
    ((__half2*)hi)[2*i]   = __half2(h0, h1);
    ((__half2*)hi)[2*i+1] = __half2(h2, h3);
    ((__half2*)lo)[2*i] = __half2(
        __float2half(v.x - __half2float(h0)),
        __float2half(v.y - __half2float(h1)));
    ((__half2*)lo)[2*i+1] = __half2(
        __float2half(v.z - __half2float(h2)),
        __float2half(v.w - __half2float(h3)));
}

// ---------------------------------------------------------------------------
// plain fp32 -> fp16 convert (hi only)
// ---------------------------------------------------------------------------
__global__ __launch_bounds__(256) void to_fp16(
    const float* __restrict__ src, __half* __restrict__ hi, int n4)
{
    int i = blockIdx.x * 256 + threadIdx.x;
    if (i >= n4) return;
    float4 v = ((const float4*)src)[i];
    ((__half2*)hi)[2*i]   = __half2(__float2half(v.x), __float2half(v.y));
    ((__half2*)hi)[2*i+1] = __half2(__float2half(v.z), __float2half(v.w));
}

// ---------------------------------------------------------------------------
// pack q_w|k_w|v_w into one [3072,2048] fp16 (hi only)
// ---------------------------------------------------------------------------
__global__ __launch_bounds__(256) void prep_wqkv(
    const float* __restrict__ qw, const float* __restrict__ kw,
    const float* __restrict__ vw, __half* __restrict__ hi)
{
    int i = blockIdx.x * 256 + threadIdx.x;
    if (i >= NQKV * DIM / 4) return;
    int row = i >> 9;
    int c4  = i & 511;
    const float* src;
    if (row < DIM)            src = qw + (size_t)row * DIM;
    else if (row < DIM + 512) src = kw + (size_t)(row - DIM) * DIM;
    else                      src = vw + (size_t)(row - DIM - 512) * DIM;
    float4 v = ((const float4*)src)[c4];
    ((__half2*)hi)[2*i]   = __half2(__float2half(v.x), __float2half(v.y));
    ((__half2*)hi)[2*i+1] = __half2(__float2half(v.z), __float2half(v.w));
}

// ---------------------------------------------------------------------------
// HMMA GEMM (NT), fp16 split. Pass 2 (Al*Bh) only for columns bn < n2.
// 128x128 CTA tile, BK=64, 8 warps, 3-stage prefetch. (R16-validated)
// ---------------------------------------------------------------------------
#define GSTAGE 32768
#define GEMM_SMEM (3 * GSTAGE)

__global__ __launch_bounds__(256) void gemm_tc(
    const __half* __restrict__ Ah, const __half* __restrict__ Al,
    const __half* __restrict__ Bh,
    float* __restrict__ C, int M, int N, int K, int n2)
{
    extern __shared__ char sm[];
    const uint32_t smem_base = s2u(sm);
    const int tid = threadIdx.x;
    const int wid = tid >> 5, lane = tid & 31;
    const int wm = wid >> 2, wn = wid & 3;
    const int bm = blockIdx.y * 128, bn = blockIdx.x * 128;

    const int kstages = K >> 6;
    const int S = (bn < n2 ? 2 : 1) * kstages;

    float acc[4][4][4];
#pragma unroll
    for (int i = 0; i < 4; ++i)
#pragma unroll
        for (int j = 0; j < 4; ++j)
#pragma unroll
            for (int t = 0; t < 4; ++t) acc[i][j][t] = 0.f;

    const int l16 = lane & 15;
    uint32_t aOff[4], aMsk[4], bOff[4], bMsk[4];
#pragma unroll
    for (int mt = 0; mt < 4; ++mt) {
        int row = wm * 64 + mt * 16 + l16;
        aOff[mt] = row * 128;
        aMsk[mt] = (row & 7) << 4;
    }
#pragma unroll
    for (int nt = 0; nt < 4; ++nt) {
        int row = wn * 32 + nt * 8 + (l16 & 7);
        bOff[nt] = row * 128;
        bMsk[nt] = (row & 7) << 4;
    }
    const uint32_t kbA = (lane >> 4) * 16;
    const uint32_t kbB = ((l16 >> 3) & 1) * 16;

    auto load_stage = [&](int s) {
        int p = s / kstages;
        int ks = (s - p * kstages) << 6;
        const __half* Ap = (p == 1) ? Al : Ah;
        uint32_t abuf = smem_base + (s % 3) * GSTAGE;
        uint32_t bbuf = abuf + 16384;
#pragma unroll
        for (int i = 0; i < 4; ++i) {
            int c = tid + i * 256;
            int row = c >> 3, c16 = c & 7;
            cp_async16(abuf + SWZ(row * 128 + c16 * 16),
                       Ap + (size_t)(bm + row) * K + ks + c16 * 8);
        }
#pragma unroll
        for (int i = 0; i < 4; ++i) {
            int c = tid + i * 256;
            int row = c >> 3, c16 = c & 7;
            cp_async16(bbuf + SWZ(row * 128 + c16 * 16),
                       Bh + (size_t)(bn + row) * K + ks + c16 * 8);
        }
        asm volatile("cp.async.commit_group;");
    };

    load_stage(0);
    load_stage(1);
    for (int s = 0; s < S; ++s) {
        if (s + 2 < S) {
            load_stage(s + 2);
            asm volatile("cp.async.wait_group 2;" ::: "memory");
        } else if (s + 1 < S) {
            asm volatile("cp.async.wait_group 1;" ::: "memory");
        } else {
            asm volatile("cp.async.wait_group 0;" ::: "memory");
        }
        __syncthreads();

        uint32_t abuf = smem_base + (s % 3) * GSTAGE;
        uint32_t bbuf = abuf + 16384;
#pragma unroll
        for (int kk = 0; kk < 4; ++kk) {
            uint32_t af[4][4], bfr[4][2];
            uint32_t ka = kk * 32 + kbA;
            uint32_t kb = kk * 32 + kbB;
#pragma unroll
            for (int mt = 0; mt < 4; ++mt)
                ldsm4(af[mt], abuf + aOff[mt] + (ka ^ aMsk[mt]));
#pragma unroll
            for (int nt = 0; nt < 4; ++nt)
                ldsm2(bfr[nt], bbuf + bOff[nt] + (kb ^ bMsk[nt]));
#pragma unroll
            for (int mt = 0; mt < 4; ++mt)
#pragma unroll
                for (int nt = 0; nt < 4; ++nt)
                    mma16816(acc[mt][nt], af[mt], bfr[nt]);
        }
        __syncthreads();
    }

    const int er = lane >> 2, ec = (lane & 3) * 2;
#pragma unroll
    for (int mt = 0; mt < 4; ++mt) {
#pragma unroll
        for (int nt = 0; nt < 4; ++nt) {
            int r0 = bm + wm * 64 + mt * 16 + er;
            int c0 = bn + wn * 32 + nt * 8 + ec;
            *(float2*)&C[(size_t)r0 * N + c0] =
                make_float2(acc[mt][nt][0], acc[mt][nt][1]);
            *(float2*)&C[(size_t)(r0 + 8) * N + c0] =
                make_float2(acc[mt][nt][2], acc[mt][nt][3]);
        }
    }
}

// ---------------------------------------------------------------------------
// RoPE tables (T x 64)
// ---------------------------------------------------------------------------
__global__ void rope_table_kernel(float* __restrict__ cs, float* __restrict__ sn)
{
    const int t = blockIdx.x, i = threadIdx.x;
    float base = 10000.f;
    if (TLEN > 1024) base = 10000.f * powf((float)TLEN / 1024.f, 128.f / 126.f);
    float l2b = log2f(base);
    float inv = exp2f(-(float)i * (l2b * (1.f / 64.f)));
    float ang = (float)t * inv;
    cs[t * 64 + i] = cosf(ang);
    sn[t * 64 + i] = sinf(ang);
}

// ---------------------------------------------------------------------------
// Fused RMSNorm + RoPE (+v pass-through), WARP-per-vector (R17).
// Block 256 = 8 warps = 8 vectors; thread holds 4 consecutive elements;
// RoPE half-exchange via shfl_xor(16). No smem, no __syncthreads.
// ---------------------------------------------------------------------------
__global__ __launch_bounds__(256) void norm_rope_kernel(
    const float* __restrict__ qkv, const float* __restrict__ q_gain,
    const float* __restrict__ cs, const float* __restrict__ sn,
    __half* __restrict__ qh, __half* __restrict__ ql,
    __half* __restrict__ kh, __half* __restrict__ vh)
{
    const int w = threadIdx.x >> 5;
    const int lane = threadIdx.x & 31;
    const int vec = blockIdx.x * 8 + w;
    const int hh = vec % 24;
    const int token = vec / 24;
    const int t = token % TLEN;

    const float* src = qkv + (size_t)token * NQKV;
    size_t off;
    float gain;
    bool isq;

    if (hh < NH) {
        src += hh * DH;
        off = ((size_t)token * NH + hh) * DH;
        gain = q_gain[hh] * (ATTN_SCALE * LOG2E);
        isq = true;
    } else if (hh < NH + NKV) {
        src += DIM + (hh - NH) * DH;
        off = ((size_t)token * NKV + (hh - NH)) * DH;
        gain = 1.f;
        isq = false;
    } else {
        src += DIM + NKV * DH + (hh - NH - NKV) * DH;
        off = ((size_t)token * NKV + (hh - NH - NKV)) * DH;
        float4 v = ((const float4*)src)[lane];
        __half2 a(__float2half(v.x), __float2half(v.y));
        __half2 b(__float2half(v.z), __float2half(v.w));
        *(uint2*)&vh[off + lane * 4] = make_uint2(*(uint32_t*)&a, *(uint32_t*)&b);
        return;
    }

    float4 xv = ((const float4*)src)[lane];
    float x[4] = {xv.x, xv.y, xv.z, xv.w};
    float s = x[0]*x[0] + x[1]*x[1] + x[2]*x[2] + x[3]*x[3];
#pragma unroll
    for (int o = 16; o > 0; o >>= 1)
        s += __shfl_xor_sync(0xffffffffu, s, o);
    float rn = rsqrtf(s * (1.f / DH) + EPSF) * gain;

    float xn[4], ox[4];
#pragma unroll
    for (int j = 0; j < 4; ++j) xn[j] = x[j] * rn;
#pragma unroll
    for (int j = 0; j < 4; ++j) ox[j] = __shfl_xor_sync(0xffffffffu, xn[j], 16);

    const int i4 = (lane & 15) * 4;
    float4 cv = *(const float4*)&cs[t * 64 + i4];
    float4 sv = *(const float4*)&sn[t * 64 + i4];
    float c[4]  = {cv.x, cv.y, cv.z, cv.w};
    float si[4] = {sv.x, sv.y, sv.z, sv.w};

    float r[4];
    if (lane < 16) {
#pragma unroll
        for (int j = 0; j < 4; ++j) r[j] = xn[j] * c[j] + ox[j] * si[j];
    } else {
#pragma unroll
        for (int j = 0; j < 4; ++j) r[j] = -ox[j] * si[j] + xn[j] * c[j];
    }

    if (isq) {
        __half h0 = __float2half(r[0]), h1 = __float2half(r[1]);
        __half h2 = __float2half(r[2]), h3 = __float2half(r[3]);
        __half2 a(h0, h1), b(h2, h3);
        *(uint2*)&qh[off + lane * 4] = make_uint2(*(uint32_t*)&a, *(uint32_t*)&b);
        __half2 la(__float2half(r[0] - __half2float(h0)),
                   __float2half(r[1] - __half2float(h1)));
        __half2 lb(__float2half(r[2] - __half2float(h2)),
                   __float2half(r[3] - __half2float(h3)));
        *(uint2*)&ql[off + lane * 4] = make_uint2(*(uint32_t*)&la, *(uint32_t*)&lb);
    } else {
        __half2 a(__float2half(r[0]), __float2half(r[1]));
        __half2 b(__float2half(r[2]), __float2half(r[3]));
        *(uint2*)&kh[off + lane * 4] = make_uint2(*(uint32_t*)&a, *(uint32_t*)&b);
    }
}

// ---------------------------------------------------------------------------
// HMMA flash attention (causal, GQA), fp16:
//   S = (qh+ql)*Kh ;  O += Ph*Vh   (P low-term dropped, R17)
// smem 64KB -> 3 CTA/SM; largest-work-first launch.
// ---------------------------------------------------------------------------
#define ATTN_SMEM (4 * 16384)

__global__ __launch_bounds__(128) void attn_mma(
    const __half* __restrict__ qh, const __half* __restrict__ ql,
    const __half* __restrict__ kh, const __half* __restrict__ vh,
    __half* __restrict__ oh, __half* __restrict__ ol)
{
    extern __shared__ char smc[];
    const uint32_t sQH = s2u(smc);
    const uint32_t sQL = sQH + 16384;
    const uint32_t sKH = sQL + 16384;
    const uint32_t sVH = sKH + 16384;

    const int qb = NQT - 1 - blockIdx.x;   // largest work first
    const int h = blockIdx.y, b = blockIdx.z;
    const int hkv = h >> 2;
    const int tid = threadIdx.x, wid = tid >> 5, lane = tid & 31;
    const int quad = lane >> 2, qx = lane & 3;
    const int q0 = qb * 64;

    const uint32_t aRow = wid * 16 + (lane & 15);
    const uint32_t aSwz = (aRow & 7) << 4;
    const uint32_t aKb  = (lane >> 4) * 16;
    const uint32_t kRowB = ((lane >> 4) & 1) * 8 + (lane & 7);
    const uint32_t kKb   = ((lane >> 3) & 1) * 16;
    const uint32_t vRowB = ((lane >> 3) & 1) * 8 + (lane & 7);
    const uint32_t vCb   = ((lane >> 4) & 1) * 16;

    for (int i = tid; i < 1024; i += 128) {
        int row = i >> 4, cb = (i & 15) * 16;
        uint32_t sw = row * 256 + (cb ^ ((row & 7) << 4));
        size_t g = ((size_t)(b * TLEN + q0 + row) * NH + h) * DH + (i & 15) * 8;
        cp_async16(sQH + sw, qh + g);
        cp_async16(sQL + sw, ql + g);
    }
    asm volatile("cp.async.commit_group;");
    asm volatile("cp.async.wait_group 0;" ::: "memory");
    __syncthreads();

    uint32_t qfh[8][4], qfl[8][4];
#pragma unroll
    for (int kk = 0; kk < 8; ++kk) {
        ldsm4(qfh[kk], sQH + aRow * 256 + ((kk * 32 + aKb) ^ aSwz));
        ldsm4(qfl[kk], sQL + aRow * 256 + ((kk * 32 + aKb) ^ aSwz));
    }

    float acc[16][4];
#pragma unroll
    for (int j = 0; j < 16; ++j)
#pragma unroll
        for (int t = 0; t < 4; ++t) acc[j][t] = 0.f;
    float m0 = -1e30f, m1 = -1e30f, l0 = 0.f, l1 = 0.f;

    for (int kt = 0; kt <= qb; ++kt) {
        __syncthreads();
        for (int i = tid; i < 1024; i += 128) {
            int row = i >> 4, cb = (i & 15) * 16;
            uint32_t sw = row * 256 + (cb ^ ((row & 7) << 4));
            size_t g = ((size_t)(b * TLEN + kt * 64 + row) * NKV + hkv) * DH
                       + (i & 15) * 8;
            cp_async16(sKH + sw, kh + g);
            cp_async16(sVH + sw, vh + g);
        }
        asm volatile("cp.async.commit_group;");
        asm volatile("cp.async.wait_group 0;" ::: "memory");
        __syncthreads();

        float s[8][4];
#pragma unroll
        for (int j = 0; j < 8; ++j)
#pragma unroll
            for (int t = 0; t < 4; ++t) s[j][t] = 0.f;

#pragma unroll
        for (int kk = 0; kk < 8; ++kk) {
#pragma unroll
            for (int jj = 0; jj < 4; ++jj) {
                uint32_t kr = jj * 16 + kRowB;
                uint32_t off = kr * 256 + ((kk * 32 + kKb) ^ ((kr & 7) << 4));
                uint32_t kf[4];
                ldsm4(kf, sKH + off);
                mma16816(s[2 * jj],     qfh[kk], kf);
                mma16816(s[2 * jj + 1], qfh[kk], kf + 2);
                mma16816(s[2 * jj],     qfl[kk], kf);
                mma16816(s[2 * jj + 1], qfl[kk], kf + 2);
            }
        }

        if (kt == qb) {
            int gr = wid * 16 + quad;
#pragma unroll
            for (int j = 0; j < 8; ++j) {
                int gc = j * 8 + qx * 2;
                if (gc     > gr)     s[j][0] = -1e30f;
                if (gc + 1 > gr)     s[j][1] = -1e30f;
                if (gc     > gr + 8) s[j][2] = -1e30f;
                if (gc + 1 > gr + 8) s[j][3] = -1e30f;
            }
        }

        float t0 = -1e30f, t1 = -1e30f;
#pragma unroll
        for (int j = 0; j < 8; ++j) {
            t0 = fmaxf(t0, fmaxf(s[j][0], s[j][1]));
            t1 = fmaxf(t1, fmaxf(s[j][2], s[j][3]));
        }
        t0 = fmaxf(t0, __shfl_xor_sync(0xffffffffu, t0, 1));
        t0 = fmaxf(t0, __shfl_xor_sync(0xffffffffu, t0, 2));
        t1 = fmaxf(t1, __shfl_xor_sync(0xffffffffu, t1, 1));
        t1 = fmaxf(t1, __shfl_xor_sync(0xffffffffu, t1, 2));
        float mn0 = fmaxf(m0, t0), mn1 = fmaxf(m1, t1);
        float sc0 = exp2f(m0 - mn0), sc1 = exp2f(m1 - mn1);
        m0 = mn0; m1 = mn1;

        uint32_t phA[8], phB[8];
        float ls0 = 0.f, ls1 = 0.f;
#pragma unroll
        for (int j = 0; j < 8; ++j) {
            float p0 = exp2f(s[j][0] - mn0);
            float p1 = exp2f(s[j][1] - mn0);
            float p2 = exp2f(s[j][2] - mn1);
            float p3 = exp2f(s[j][3] - mn1);
            ls0 += p0 + p1; ls1 += p2 + p3;
            __half2 a(__float2half(p0), __float2half(p1));
            __half2 bb(__float2half(p2), __float2half(p3));
            phA[j] = *(uint32_t*)&a; phB[j] = *(uint32_t*)&bb;
        }
        l0 = l0 * sc0 + ls0;
        l1 = l1 * sc1 + ls1;
#pragma unroll
        for (int j = 0; j < 16; ++j) {
            acc[j][0] *= sc0; acc[j][1] *= sc0;
            acc[j][2] *= sc1; acc[j][3] *= sc1;
        }

#pragma unroll
        for (int kk = 0; kk < 4; ++kk) {
            uint32_t aH[4] = {phA[2*kk], phB[2*kk], phA[2*kk+1], phB[2*kk+1]};
            uint32_t vr = kk * 16 + vRowB;
            uint32_t vsw = (vr & 7) << 4;
#pragma unroll
            for (int jp = 0; jp < 8; ++jp) {
                uint32_t off = vr * 256 + ((jp * 32 + vCb) ^ vsw);
                uint32_t vf[4];
                ldsm4t(vf, sVH + off);
                mma16816(acc[2 * jp],     aH, vf);
                mma16816(acc[2 * jp + 1], aH, vf + 2);
            }
        }
    }

    l0 += __shfl_xor_sync(0xffffffffu, l0, 1);
    l0 += __shfl_xor_sync(0xffffffffu, l0, 2);
    l1 += __shfl_xor_sync(0xffffffffu, l1, 1);
    l1 += __shfl_xor_sync(0xffffffffu, l1, 2);
    float i0 = 1.f / l0, i1 = 1.f / l1;

    size_t tok0 = (size_t)(b * TLEN + q0 + wid * 16 + quad);
    size_t tok1 = tok0 + 8;
#pragma unroll
    for (int j = 0; j < 16; ++j) {
        int col = h * DH + j * 8 + qx * 2;
        float v0 = acc[j][0] * i0, v1 = acc[j][1] * i0;
        float v2 = acc[j][2] * i1, v3 = acc[j][3] * i1;
        __half h0 = __float2half(v0), h1 = __float2half(v1);
        __half h2 = __float2half(v2), h3 = __float2half(v3);
        *(__half2*)&oh[tok0 * DIM + col] = __half2(h0, h1);
        *(__half2*)&oh[tok1 * DIM + col] = __half2(h2, h3);
        *(__half2*)&ol[tok0 * DIM + col] =
            __half2(__float2half(v0 - __half2float(h0)),
                    __float2half(v1 - __half2float(h1)));
        *(__half2*)&ol[tok1 * DIM + col] =
            __half2(__float2half(v2 - __half2float(h2)),
                    __float2half(v3 - __half2float(h3)));
    }
}

// ---------------------------------------------------------------------------
extern "C" void kernel_launch(void* const* d_in, const int* in_sizes, int n_in,
                              void* d_out, int out_size)
{
    const float* x  = (const float*)d_in[0];
    const float* qw = (const float*)d_in[1];
    const float* kw = (const float*)d_in[2];
    const float* vw = (const float*)d_in[3];
    const float* ow = (const float*)d_in[4];
    const float* qg = (const float*)d_in[5];
    float* out = (float*)d_out;

    float *gqkv, *gcos, *gsin;
    cudaGetSymbolAddress((void**)&gqkv, g_qkv);
    cudaGetSymbolAddress((void**)&gcos, g_cos);
    cudaGetSymbolAddress((void**)&gsin, g_sin);

    __half *xh, *xl, *wqh, *owh, *oh, *ol;
    __half *qbh, *qbl, *kbh, *vbh;
    cudaGetSymbolAddress((void**)&xh,  g_xh);    cudaGetSymbolAddress((void**)&xl,  g_xl);
    cudaGetSymbolAddress((void**)&wqh, g_wqkvh);
    cudaGetSymbolAddress((void**)&owh, g_owh);
    cudaGetSymbolAddress((void**)&oh,  g_oh);    cudaGetSymbolAddress((void**)&ol,  g_ol);
    cudaGetSymbolAddress((void**)&qbh, g_qbh);   cudaGetSymbolAddress((void**)&qbl, g_qbl);
    cudaGetSymbolAddress((void**)&kbh, g_kbh);   cudaGetSymbolAddress((void**)&vbh, g_vbh);

    const int M = MTOT, K = DIM;

    cudaFuncSetAttribute(gemm_tc, cudaFuncAttributeMaxDynamicSharedMemorySize, GEMM_SMEM);
    cudaFuncSetAttribute(attn_mma, cudaFuncAttributeMaxDynamicSharedMemorySize, ATTN_SMEM);

    rope_table_kernel<<<TLEN, 64>>>(gcos, gsin);                           // 0
    split_fp16<<<(M*K/4 + 255)/256, 256>>>(x, xh, xl, M*K/4);              // 1
    prep_wqkv<<<(NQKV*DIM/4 + 255)/256, 256>>>(qw, kw, vw, wqh);           // 2
    gemm_tc<<<dim3(NQKV/128, M/128), 256, GEMM_SMEM>>>(                     // 3
        xh, xl, wqh, gqkv, M, NQKV, K, DIM);
    norm_rope_kernel<<<M * 24 / 8, 256>>>(gqkv, qg, gcos, gsin,            // 4
                                          qbh, qbl, kbh, vbh);
    attn_mma<<<dim3(NQT, NH, BATCH), 128, ATTN_SMEM>>>(                     // 5
        qbh, qbl, kbh, vbh, oh, ol);
    to_fp16<<<(DIM*DIM/4 + 255)/256, 256>>>(ow, owh, DIM*DIM/4);           // 6
    gemm_tc<<<dim3(DIM/128, M/128), 256, GEMM_SMEM>>>(                      // 7
        oh, ol, owh, out, M, DIM, K, DIM);
}